// round 1
// baseline (speedup 1.0000x reference)
#include <cuda_runtime.h>
#include <math.h>

#define BATCH 8
#define CIN   256
#define NTOK  4096
#define CKD   128
#define CVD   128

// Scratch (allocation-free rule: __device__ globals). 4 x 16MB.
__device__ float g_Q[BATCH * NTOK * CKD];
__device__ float g_K[BATCH * NTOK * CKD];
__device__ float g_V[BATCH * NTOK * CVD];
__device__ float g_Y[BATCH * NTOK * CVD];

// ---------------------------------------------------------------------------
// Projections: out[b,n,k] = sum_c x[b,c,n] * w[k,c] + bias[k]
// grid (NTOK/128, BATCH, 3), block 256. Tile 128n x 128k, kTile=16 over c.
// ---------------------------------------------------------------------------
__global__ __launch_bounds__(256) void proj_kernel(
    const float* __restrict__ x,
    const float* __restrict__ tw, const float* __restrict__ tb,
    const float* __restrict__ pw, const float* __restrict__ pb,
    const float* __restrict__ gw, const float* __restrict__ gb)
{
    const int b     = blockIdx.y;
    const int which = blockIdx.z;
    const float* w; const float* bias; float* out;
    if (which == 0)      { w = tw; bias = tb; out = g_Q; }
    else if (which == 1) { w = pw; bias = pb; out = g_K; }
    else                 { w = gw; bias = gb; out = g_V; }
    const float* xb = x + (size_t)b * CIN * NTOK;
    out += (size_t)b * NTOK * CKD;
    const int n0 = blockIdx.x * 128;

    __shared__ float As[16][128];  // [cc][n]
    __shared__ float Bs[16][128];  // [cc][k]

    const int t  = threadIdx.x;
    const int ty = t >> 4;
    const int tx = t & 15;

    float acc[8][8];
    #pragma unroll
    for (int i = 0; i < 8; i++)
        #pragma unroll
        for (int j = 0; j < 8; j++) acc[i][j] = 0.f;

    for (int c0 = 0; c0 < CIN; c0 += 16) {
        // load x tile: 16 c-rows x 128 n, coalesced along n
        #pragma unroll
        for (int r = 0; r < 2; r++) {
            int idx = t + r * 256;
            int cc  = idx >> 5;
            int n4  = (idx & 31) << 2;
            *(float4*)&As[cc][n4] =
                *(const float4*)&xb[(size_t)(c0 + cc) * NTOK + n0 + n4];
        }
        // load w tile: 128 k x 16 c, each thread 8 contiguous c's for one k
        {
            int k  = t & 127;
            int cg = (t >> 7) << 3;
            float4 w0 = *(const float4*)&w[(size_t)k * CIN + c0 + cg];
            float4 w1 = *(const float4*)&w[(size_t)k * CIN + c0 + cg + 4];
            Bs[cg + 0][k] = w0.x; Bs[cg + 1][k] = w0.y;
            Bs[cg + 2][k] = w0.z; Bs[cg + 3][k] = w0.w;
            Bs[cg + 4][k] = w1.x; Bs[cg + 5][k] = w1.y;
            Bs[cg + 6][k] = w1.z; Bs[cg + 7][k] = w1.w;
        }
        __syncthreads();
        #pragma unroll
        for (int cc = 0; cc < 16; cc++) {
            float a[8], bb[8];
            *(float4*)&a[0]  = *(const float4*)&As[cc][ty * 8];
            *(float4*)&a[4]  = *(const float4*)&As[cc][ty * 8 + 4];
            *(float4*)&bb[0] = *(const float4*)&Bs[cc][tx * 4];
            *(float4*)&bb[4] = *(const float4*)&Bs[cc][64 + tx * 4];
            #pragma unroll
            for (int i = 0; i < 8; i++)
                #pragma unroll
                for (int j = 0; j < 8; j++)
                    acc[i][j] = fmaf(a[i], bb[j], acc[i][j]);
        }
        __syncthreads();
    }

    float b0[4], b1[4];
    #pragma unroll
    for (int j = 0; j < 4; j++) {
        b0[j] = bias[tx * 4 + j];
        b1[j] = bias[64 + tx * 4 + j];
    }
    #pragma unroll
    for (int i = 0; i < 8; i++) {
        size_t row = (size_t)(n0 + ty * 8 + i);
        float4 r0 = make_float4(acc[i][0] + b0[0], acc[i][1] + b0[1],
                                acc[i][2] + b0[2], acc[i][3] + b0[3]);
        float4 r1 = make_float4(acc[i][4] + b1[0], acc[i][5] + b1[1],
                                acc[i][6] + b1[2], acc[i][7] + b1[3]);
        *(float4*)&out[row * CKD + tx * 4]      = r0;
        *(float4*)&out[row * CKD + 64 + tx * 4] = r1;
    }
}

// ---------------------------------------------------------------------------
// Flash attention, fp32, BQ=BK=64, D=DV=128.
// grid (NTOK/64, BATCH), block 256, dynamic smem ~114KB.
// Thread (ty,tx) in 16x16: owns q-rows ty*4+i; S k-cols tx+16j; V cols tx*4 / 64+tx*4.
// Rows map to 16-lane half-warps -> shfl reductions; m/l stay in registers.
// ---------------------------------------------------------------------------
__global__ __launch_bounds__(256) void flash_kernel()
{
    extern __shared__ float sm[];
    float* Qs = sm;               // 64 x 132 (padded)
    float* Ks = Qs + 64 * 132;    // 64 x 132 (padded)
    float* Vs = Ks + 64 * 132;    // 64 x 128
    float* Ps = Vs + 64 * 128;    // 64 x 64

    const int b  = blockIdx.y;
    const int q0 = blockIdx.x * 64;
    const int t  = threadIdx.x;
    const int ty = t >> 4;
    const int tx = t & 15;

    const float* Qg = g_Q + ((size_t)b * NTOK + q0) * CKD;
    const float* Kg = g_K + (size_t)b * NTOK * CKD;
    const float* Vg = g_V + (size_t)b * NTOK * CVD;

    // load Q tile (64 x 128)
    for (int idx = t; idx < 64 * 32; idx += 256) {
        int r  = idx >> 5;
        int c4 = (idx & 31) << 2;
        *(float4*)&Qs[r * 132 + c4] = *(const float4*)&Qg[(size_t)r * CKD + c4];
    }

    float o[4][8];
    float m[4], l[4];
    #pragma unroll
    for (int i = 0; i < 4; i++) {
        m[i] = -INFINITY; l[i] = 0.f;
        #pragma unroll
        for (int j = 0; j < 8; j++) o[i][j] = 0.f;
    }

    for (int kt = 0; kt < NTOK / 64; kt++) {
        __syncthreads();  // prev PV done (and Q load on first iter)
        const float* Kt = Kg + (size_t)kt * 64 * CKD;
        const float* Vt = Vg + (size_t)kt * 64 * CVD;
        for (int idx = t; idx < 2048; idx += 256) {
            int r  = idx >> 5;
            int c4 = (idx & 31) << 2;
            *(float4*)&Ks[r * 132 + c4] = *(const float4*)&Kt[(size_t)r * CKD + c4];
            *(float4*)&Vs[r * 128 + c4] = *(const float4*)&Vt[(size_t)r * CVD + c4];
        }
        __syncthreads();

        // S = Q K^T  (64x64, K=128)
        float s[4][4];
        #pragma unroll
        for (int i = 0; i < 4; i++)
            #pragma unroll
            for (int j = 0; j < 4; j++) s[i][j] = 0.f;

        #pragma unroll 4
        for (int c = 0; c < 128; c += 4) {
            float4 q[4], kk[4];
            #pragma unroll
            for (int i = 0; i < 4; i++)
                q[i] = *(const float4*)&Qs[(ty * 4 + i) * 132 + c];
            #pragma unroll
            for (int j = 0; j < 4; j++)
                kk[j] = *(const float4*)&Ks[(tx + 16 * j) * 132 + c];
            #pragma unroll
            for (int i = 0; i < 4; i++)
                #pragma unroll
                for (int j = 0; j < 4; j++) {
                    s[i][j] = fmaf(q[i].x, kk[j].x, s[i][j]);
                    s[i][j] = fmaf(q[i].y, kk[j].y, s[i][j]);
                    s[i][j] = fmaf(q[i].z, kk[j].z, s[i][j]);
                    s[i][j] = fmaf(q[i].w, kk[j].w, s[i][j]);
                }
        }

        // online softmax (per-row over 16 lanes sharing ty)
        #pragma unroll
        for (int i = 0; i < 4; i++) {
            float mloc = fmaxf(fmaxf(s[i][0], s[i][1]), fmaxf(s[i][2], s[i][3]));
            #pragma unroll
            for (int off = 8; off > 0; off >>= 1)
                mloc = fmaxf(mloc, __shfl_xor_sync(0xffffffffu, mloc, off));
            float mnew = fmaxf(m[i], mloc);
            float corr = __expf(m[i] - mnew);
            float ps = 0.f;
            #pragma unroll
            for (int j = 0; j < 4; j++) {
                float p = __expf(s[i][j] - mnew);
                Ps[(ty * 4 + i) * 64 + tx + 16 * j] = p;
                ps += p;
            }
            #pragma unroll
            for (int off = 8; off > 0; off >>= 1)
                ps += __shfl_xor_sync(0xffffffffu, ps, off);
            l[i] = l[i] * corr + ps;
            m[i] = mnew;
            #pragma unroll
            for (int j = 0; j < 8; j++) o[i][j] *= corr;
        }
        __syncwarp();  // Ps producer == consumer half-warp; warp sync suffices

        // O += P V  (64x128, K=64)
        #pragma unroll 2
        for (int k = 0; k < 64; k++) {
            float4 v0 = *(const float4*)&Vs[k * 128 + tx * 4];
            float4 v1 = *(const float4*)&Vs[k * 128 + 64 + tx * 4];
            #pragma unroll
            for (int i = 0; i < 4; i++) {
                float p = Ps[(ty * 4 + i) * 64 + k];
                o[i][0] = fmaf(p, v0.x, o[i][0]);
                o[i][1] = fmaf(p, v0.y, o[i][1]);
                o[i][2] = fmaf(p, v0.z, o[i][2]);
                o[i][3] = fmaf(p, v0.w, o[i][3]);
                o[i][4] = fmaf(p, v1.x, o[i][4]);
                o[i][5] = fmaf(p, v1.y, o[i][5]);
                o[i][6] = fmaf(p, v1.z, o[i][6]);
                o[i][7] = fmaf(p, v1.w, o[i][7]);
            }
        }
    }

    float* Yg = g_Y + ((size_t)b * NTOK + q0) * CVD;
    #pragma unroll
    for (int i = 0; i < 4; i++) {
        float inv = 1.f / l[i];
        float4 r0 = make_float4(o[i][0] * inv, o[i][1] * inv,
                                o[i][2] * inv, o[i][3] * inv);
        float4 r1 = make_float4(o[i][4] * inv, o[i][5] * inv,
                                o[i][6] * inv, o[i][7] * inv);
        *(float4*)&Yg[(size_t)(ty * 4 + i) * CVD + tx * 4]      = r0;
        *(float4*)&Yg[(size_t)(ty * 4 + i) * CVD + 64 + tx * 4] = r1;
    }
}

// ---------------------------------------------------------------------------
// Output conv: out[b,c,n] = sum_v Y[b,n,v] * w_w[c,v] + w_b[c]
// grid (NTOK/128, CIN/128, BATCH), block 256. Tile 128c x 128n, kTile=16 over v.
// ---------------------------------------------------------------------------
__global__ __launch_bounds__(256) void out_kernel(
    const float* __restrict__ ww, const float* __restrict__ wb,
    float* __restrict__ out)
{
    const int b  = blockIdx.z;
    const int c0 = blockIdx.y * 128;
    const int n0 = blockIdx.x * 128;

    __shared__ float Ws[16][128];  // [vv][c]
    __shared__ float Ys[16][128];  // [vv][n]

    const float* Yb = g_Y + (size_t)b * NTOK * CVD;
    float* ob = out + (size_t)b * CIN * NTOK;

    const int t  = threadIdx.x;
    const int ty = t >> 4;
    const int tx = t & 15;

    float acc[8][8];
    #pragma unroll
    for (int i = 0; i < 8; i++)
        #pragma unroll
        for (int j = 0; j < 8; j++) acc[i][j] = 0.f;

    for (int v0 = 0; v0 < CVD; v0 += 16) {
        {
            int cn = t >> 1;            // c (or n) index 0..127
            int vg = (t & 1) << 3;      // 0 or 8
            float4 w0 = *(const float4*)&ww[(size_t)(c0 + cn) * CVD + v0 + vg];
            float4 w1 = *(const float4*)&ww[(size_t)(c0 + cn) * CVD + v0 + vg + 4];
            Ws[vg + 0][cn] = w0.x; Ws[vg + 1][cn] = w0.y;
            Ws[vg + 2][cn] = w0.z; Ws[vg + 3][cn] = w0.w;
            Ws[vg + 4][cn] = w1.x; Ws[vg + 5][cn] = w1.y;
            Ws[vg + 6][cn] = w1.z; Ws[vg + 7][cn] = w1.w;
            float4 y0 = *(const float4*)&Yb[(size_t)(n0 + cn) * CVD + v0 + vg];
            float4 y1 = *(const float4*)&Yb[(size_t)(n0 + cn) * CVD + v0 + vg + 4];
            Ys[vg + 0][cn] = y0.x; Ys[vg + 1][cn] = y0.y;
            Ys[vg + 2][cn] = y0.z; Ys[vg + 3][cn] = y0.w;
            Ys[vg + 4][cn] = y1.x; Ys[vg + 5][cn] = y1.y;
            Ys[vg + 6][cn] = y1.z; Ys[vg + 7][cn] = y1.w;
        }
        __syncthreads();
        #pragma unroll
        for (int vv = 0; vv < 16; vv++) {
            float a[8], bb[8];
            *(float4*)&a[0]  = *(const float4*)&Ws[vv][ty * 8];
            *(float4*)&a[4]  = *(const float4*)&Ws[vv][ty * 8 + 4];
            *(float4*)&bb[0] = *(const float4*)&Ys[vv][tx * 4];
            *(float4*)&bb[4] = *(const float4*)&Ys[vv][64 + tx * 4];
            #pragma unroll
            for (int i = 0; i < 8; i++)
                #pragma unroll
                for (int j = 0; j < 8; j++)
                    acc[i][j] = fmaf(a[i], bb[j], acc[i][j]);
        }
        __syncthreads();
    }

    #pragma unroll
    for (int i = 0; i < 8; i++) {
        int c = c0 + ty * 8 + i;
        float bv = wb[c];
        float4 r0 = make_float4(acc[i][0] + bv, acc[i][1] + bv,
                                acc[i][2] + bv, acc[i][3] + bv);
        float4 r1 = make_float4(acc[i][4] + bv, acc[i][5] + bv,
                                acc[i][6] + bv, acc[i][7] + bv);
        *(float4*)&ob[(size_t)c * NTOK + n0 + tx * 4]      = r0;
        *(float4*)&ob[(size_t)c * NTOK + n0 + 64 + tx * 4] = r1;
    }
}

// ---------------------------------------------------------------------------
extern "C" void kernel_launch(void* const* d_in, const int* in_sizes, int n_in,
                              void* d_out, int out_size)
{
    const float* x  = (const float*)d_in[0];
    const float* tw = (const float*)d_in[1];
    const float* tb = (const float*)d_in[2];
    const float* pw = (const float*)d_in[3];
    const float* pb = (const float*)d_in[4];
    const float* gw = (const float*)d_in[5];
    const float* gb = (const float*)d_in[6];
    const float* ww = (const float*)d_in[7];
    const float* wb = (const float*)d_in[8];
    float* out = (float*)d_out;

    (void)in_sizes; (void)n_in; (void)out_size;

    proj_kernel<<<dim3(NTOK / 128, BATCH, 3), 256>>>(x, tw, tb, pw, pb, gw, gb);

    const int flash_smem = (64 * 132 + 64 * 132 + 64 * 128 + 64 * 64) * (int)sizeof(float);
    cudaFuncSetAttribute(flash_kernel,
                         cudaFuncAttributeMaxDynamicSharedMemorySize, flash_smem);
    flash_kernel<<<dim3(NTOK / 64, BATCH), 256, flash_smem>>>();

    out_kernel<<<dim3(NTOK / 128, CIN / 128, BATCH), 256>>>(ww, wb, out);
}

// round 2
// speedup vs baseline: 1.0001x; 1.0001x over previous
#include <cuda_runtime.h>
#include <math.h>

#define BATCH 8
#define CIN   256
#define NTOK  4096
#define CKD   128
#define CVD   128

// Scratch (allocation-free rule: __device__ globals). 4 x 16MB.
__device__ float g_Q[BATCH * NTOK * CKD];
__device__ float g_K[BATCH * NTOK * CKD];
__device__ float g_V[BATCH * NTOK * CVD];
__device__ float g_Y[BATCH * NTOK * CVD];

// ---------------------------------------------------------------------------
// Projections: out[b,n,k] = sum_c x[b,c,n] * w[k,c] + bias[k]
// grid (NTOK/128, BATCH, 3), block 256. Tile 128n x 128k, kTile=16 over c.
// ---------------------------------------------------------------------------
__global__ __launch_bounds__(256) void proj_kernel(
    const float* __restrict__ x,
    const float* __restrict__ tw, const float* __restrict__ tb,
    const float* __restrict__ pw, const float* __restrict__ pb,
    const float* __restrict__ gw, const float* __restrict__ gb)
{
    const int b     = blockIdx.y;
    const int which = blockIdx.z;
    const float* w; const float* bias; float* out;
    if (which == 0)      { w = tw; bias = tb; out = g_Q; }
    else if (which == 1) { w = pw; bias = pb; out = g_K; }
    else                 { w = gw; bias = gb; out = g_V; }
    const float* xb = x + (size_t)b * CIN * NTOK;
    out += (size_t)b * NTOK * CKD;
    const int n0 = blockIdx.x * 128;

    __shared__ float As[16][128];  // [cc][n]
    __shared__ float Bs[16][128];  // [cc][k]

    const int t  = threadIdx.x;
    const int ty = t >> 4;
    const int tx = t & 15;

    float acc[8][8];
    #pragma unroll
    for (int i = 0; i < 8; i++)
        #pragma unroll
        for (int j = 0; j < 8; j++) acc[i][j] = 0.f;

    for (int c0 = 0; c0 < CIN; c0 += 16) {
        // load x tile: 16 c-rows x 128 n, coalesced along n
        #pragma unroll
        for (int r = 0; r < 2; r++) {
            int idx = t + r * 256;
            int cc  = idx >> 5;
            int n4  = (idx & 31) << 2;
            *(float4*)&As[cc][n4] =
                *(const float4*)&xb[(size_t)(c0 + cc) * NTOK + n0 + n4];
        }
        // load w tile: 128 k x 16 c, each thread 8 contiguous c's for one k
        {
            int k  = t & 127;
            int cg = (t >> 7) << 3;
            float4 w0 = *(const float4*)&w[(size_t)k * CIN + c0 + cg];
            float4 w1 = *(const float4*)&w[(size_t)k * CIN + c0 + cg + 4];
            Bs[cg + 0][k] = w0.x; Bs[cg + 1][k] = w0.y;
            Bs[cg + 2][k] = w0.z; Bs[cg + 3][k] = w0.w;
            Bs[cg + 4][k] = w1.x; Bs[cg + 5][k] = w1.y;
            Bs[cg + 6][k] = w1.z; Bs[cg + 7][k] = w1.w;
        }
        __syncthreads();
        #pragma unroll
        for (int cc = 0; cc < 16; cc++) {
            float a[8], bb[8];
            *(float4*)&a[0]  = *(const float4*)&As[cc][ty * 8];
            *(float4*)&a[4]  = *(const float4*)&As[cc][ty * 8 + 4];
            *(float4*)&bb[0] = *(const float4*)&Bs[cc][tx * 4];
            *(float4*)&bb[4] = *(const float4*)&Bs[cc][64 + tx * 4];
            #pragma unroll
            for (int i = 0; i < 8; i++)
                #pragma unroll
                for (int j = 0; j < 8; j++)
                    acc[i][j] = fmaf(a[i], bb[j], acc[i][j]);
        }
        __syncthreads();
    }

    float b0[4], b1[4];
    #pragma unroll
    for (int j = 0; j < 4; j++) {
        b0[j] = bias[tx * 4 + j];
        b1[j] = bias[64 + tx * 4 + j];
    }
    #pragma unroll
    for (int i = 0; i < 8; i++) {
        size_t row = (size_t)(n0 + ty * 8 + i);
        float4 r0 = make_float4(acc[i][0] + b0[0], acc[i][1] + b0[1],
                                acc[i][2] + b0[2], acc[i][3] + b0[3]);
        float4 r1 = make_float4(acc[i][4] + b1[0], acc[i][5] + b1[1],
                                acc[i][6] + b1[2], acc[i][7] + b1[3]);
        *(float4*)&out[row * CKD + tx * 4]      = r0;
        *(float4*)&out[row * CKD + 64 + tx * 4] = r1;
    }
}

// ---------------------------------------------------------------------------
// Flash attention, fp32, BQ=BK=64, D=DV=128.
// grid (NTOK/64, BATCH), block 256, dynamic smem ~114KB.
// Thread (ty,tx) in 16x16: owns q-rows ty*4+i; S k-cols tx+16j; V cols tx*4 / 64+tx*4.
// Rows map to 16-lane half-warps -> shfl reductions; m/l stay in registers.
// ---------------------------------------------------------------------------
__global__ __launch_bounds__(256) void flash_kernel()
{
    extern __shared__ float sm[];
    float* Qs = sm;               // 64 x 132 (padded)
    float* Ks = Qs + 64 * 132;    // 64 x 132 (padded)
    float* Vs = Ks + 64 * 132;    // 64 x 128
    float* Ps = Vs + 64 * 128;    // 64 x 64

    const int b  = blockIdx.y;
    const int q0 = blockIdx.x * 64;
    const int t  = threadIdx.x;
    const int ty = t >> 4;
    const int tx = t & 15;

    const float* Qg = g_Q + ((size_t)b * NTOK + q0) * CKD;
    const float* Kg = g_K + (size_t)b * NTOK * CKD;
    const float* Vg = g_V + (size_t)b * NTOK * CVD;

    // load Q tile (64 x 128)
    for (int idx = t; idx < 64 * 32; idx += 256) {
        int r  = idx >> 5;
        int c4 = (idx & 31) << 2;
        *(float4*)&Qs[r * 132 + c4] = *(const float4*)&Qg[(size_t)r * CKD + c4];
    }

    float o[4][8];
    float m[4], l[4];
    #pragma unroll
    for (int i = 0; i < 4; i++) {
        m[i] = -INFINITY; l[i] = 0.f;
        #pragma unroll
        for (int j = 0; j < 8; j++) o[i][j] = 0.f;
    }

    for (int kt = 0; kt < NTOK / 64; kt++) {
        __syncthreads();  // prev PV done (and Q load on first iter)
        const float* Kt = Kg + (size_t)kt * 64 * CKD;
        const float* Vt = Vg + (size_t)kt * 64 * CVD;
        for (int idx = t; idx < 2048; idx += 256) {
            int r  = idx >> 5;
            int c4 = (idx & 31) << 2;
            *(float4*)&Ks[r * 132 + c4] = *(const float4*)&Kt[(size_t)r * CKD + c4];
            *(float4*)&Vs[r * 128 + c4] = *(const float4*)&Vt[(size_t)r * CVD + c4];
        }
        __syncthreads();

        // S = Q K^T  (64x64, K=128)
        float s[4][4];
        #pragma unroll
        for (int i = 0; i < 4; i++)
            #pragma unroll
            for (int j = 0; j < 4; j++) s[i][j] = 0.f;

        #pragma unroll 4
        for (int c = 0; c < 128; c += 4) {
            float4 q[4], kk[4];
            #pragma unroll
            for (int i = 0; i < 4; i++)
                q[i] = *(const float4*)&Qs[(ty * 4 + i) * 132 + c];
            #pragma unroll
            for (int j = 0; j < 4; j++)
                kk[j] = *(const float4*)&Ks[(tx + 16 * j) * 132 + c];
            #pragma unroll
            for (int i = 0; i < 4; i++)
                #pragma unroll
                for (int j = 0; j < 4; j++) {
                    s[i][j] = fmaf(q[i].x, kk[j].x, s[i][j]);
                    s[i][j] = fmaf(q[i].y, kk[j].y, s[i][j]);
                    s[i][j] = fmaf(q[i].z, kk[j].z, s[i][j]);
                    s[i][j] = fmaf(q[i].w, kk[j].w, s[i][j]);
                }
        }

        // online softmax (per-row over 16 lanes sharing ty)
        #pragma unroll
        for (int i = 0; i < 4; i++) {
            float mloc = fmaxf(fmaxf(s[i][0], s[i][1]), fmaxf(s[i][2], s[i][3]));
            #pragma unroll
            for (int off = 8; off > 0; off >>= 1)
                mloc = fmaxf(mloc, __shfl_xor_sync(0xffffffffu, mloc, off));
            float mnew = fmaxf(m[i], mloc);
            float corr = __expf(m[i] - mnew);
            float ps = 0.f;
            #pragma unroll
            for (int j = 0; j < 4; j++) {
                float p = __expf(s[i][j] - mnew);
                Ps[(ty * 4 + i) * 64 + tx + 16 * j] = p;
                ps += p;
            }
            #pragma unroll
            for (int off = 8; off > 0; off >>= 1)
                ps += __shfl_xor_sync(0xffffffffu, ps, off);
            l[i] = l[i] * corr + ps;
            m[i] = mnew;
            #pragma unroll
            for (int j = 0; j < 8; j++) o[i][j] *= corr;
        }
        __syncwarp();  // Ps producer == consumer half-warp; warp sync suffices

        // O += P V  (64x128, K=64)
        #pragma unroll 2
        for (int k = 0; k < 64; k++) {
            float4 v0 = *(const float4*)&Vs[k * 128 + tx * 4];
            float4 v1 = *(const float4*)&Vs[k * 128 + 64 + tx * 4];
            #pragma unroll
            for (int i = 0; i < 4; i++) {
                float p = Ps[(ty * 4 + i) * 64 + k];
                o[i][0] = fmaf(p, v0.x, o[i][0]);
                o[i][1] = fmaf(p, v0.y, o[i][1]);
                o[i][2] = fmaf(p, v0.z, o[i][2]);
                o[i][3] = fmaf(p, v0.w, o[i][3]);
                o[i][4] = fmaf(p, v1.x, o[i][4]);
                o[i][5] = fmaf(p, v1.y, o[i][5]);
                o[i][6] = fmaf(p, v1.z, o[i][6]);
                o[i][7] = fmaf(p, v1.w, o[i][7]);
            }
        }
    }

    float* Yg = g_Y + ((size_t)b * NTOK + q0) * CVD;
    #pragma unroll
    for (int i = 0; i < 4; i++) {
        float inv = 1.f / l[i];
        float4 r0 = make_float4(o[i][0] * inv, o[i][1] * inv,
                                o[i][2] * inv, o[i][3] * inv);
        float4 r1 = make_float4(o[i][4] * inv, o[i][5] * inv,
                                o[i][6] * inv, o[i][7] * inv);
        *(float4*)&Yg[(size_t)(ty * 4 + i) * CVD + tx * 4]      = r0;
        *(float4*)&Yg[(size_t)(ty * 4 + i) * CVD + 64 + tx * 4] = r1;
    }
}

// ---------------------------------------------------------------------------
// Output conv: out[b,c,n] = sum_v Y[b,n,v] * w_w[c,v] + w_b[c]
// grid (NTOK/128, CIN/128, BATCH), block 256. Tile 128c x 128n, kTile=16 over v.
// ---------------------------------------------------------------------------
__global__ __launch_bounds__(256) void out_kernel(
    const float* __restrict__ ww, const float* __restrict__ wb,
    float* __restrict__ out)
{
    const int b  = blockIdx.z;
    const int c0 = blockIdx.y * 128;
    const int n0 = blockIdx.x * 128;

    __shared__ float Ws[16][128];  // [vv][c]
    __shared__ float Ys[16][128];  // [vv][n]

    const float* Yb = g_Y + (size_t)b * NTOK * CVD;
    float* ob = out + (size_t)b * CIN * NTOK;

    const int t  = threadIdx.x;
    const int ty = t >> 4;
    const int tx = t & 15;

    float acc[8][8];
    #pragma unroll
    for (int i = 0; i < 8; i++)
        #pragma unroll
        for (int j = 0; j < 8; j++) acc[i][j] = 0.f;

    for (int v0 = 0; v0 < CVD; v0 += 16) {
        {
            int cn = t >> 1;            // c (or n) index 0..127
            int vg = (t & 1) << 3;      // 0 or 8
            float4 w0 = *(const float4*)&ww[(size_t)(c0 + cn) * CVD + v0 + vg];
            float4 w1 = *(const float4*)&ww[(size_t)(c0 + cn) * CVD + v0 + vg + 4];
            Ws[vg + 0][cn] = w0.x; Ws[vg + 1][cn] = w0.y;
            Ws[vg + 2][cn] = w0.z; Ws[vg + 3][cn] = w0.w;
            Ws[vg + 4][cn] = w1.x; Ws[vg + 5][cn] = w1.y;
            Ws[vg + 6][cn] = w1.z; Ws[vg + 7][cn] = w1.w;
            float4 y0 = *(const float4*)&Yb[(size_t)(n0 + cn) * CVD + v0 + vg];
            float4 y1 = *(const float4*)&Yb[(size_t)(n0 + cn) * CVD + v0 + vg + 4];
            Ys[vg + 0][cn] = y0.x; Ys[vg + 1][cn] = y0.y;
            Ys[vg + 2][cn] = y0.z; Ys[vg + 3][cn] = y0.w;
            Ys[vg + 4][cn] = y1.x; Ys[vg + 5][cn] = y1.y;
            Ys[vg + 6][cn] = y1.z; Ys[vg + 7][cn] = y1.w;
        }
        __syncthreads();
        #pragma unroll
        for (int vv = 0; vv < 16; vv++) {
            float a[8], bb[8];
            *(float4*)&a[0]  = *(const float4*)&Ws[vv][ty * 8];
            *(float4*)&a[4]  = *(const float4*)&Ws[vv][ty * 8 + 4];
            *(float4*)&bb[0] = *(const float4*)&Ys[vv][tx * 4];
            *(float4*)&bb[4] = *(const float4*)&Ys[vv][64 + tx * 4];
            #pragma unroll
            for (int i = 0; i < 8; i++)
                #pragma unroll
                for (int j = 0; j < 8; j++)
                    acc[i][j] = fmaf(a[i], bb[j], acc[i][j]);
        }
        __syncthreads();
    }

    #pragma unroll
    for (int i = 0; i < 8; i++) {
        int c = c0 + ty * 8 + i;
        float bv = wb[c];
        float4 r0 = make_float4(acc[i][0] + bv, acc[i][1] + bv,
                                acc[i][2] + bv, acc[i][3] + bv);
        float4 r1 = make_float4(acc[i][4] + bv, acc[i][5] + bv,
                                acc[i][6] + bv, acc[i][7] + bv);
        *(float4*)&ob[(size_t)c * NTOK + n0 + tx * 4]      = r0;
        *(float4*)&ob[(size_t)c * NTOK + n0 + 64 + tx * 4] = r1;
    }
}

// ---------------------------------------------------------------------------
extern "C" void kernel_launch(void* const* d_in, const int* in_sizes, int n_in,
                              void* d_out, int out_size)
{
    const float* x  = (const float*)d_in[0];
    const float* tw = (const float*)d_in[1];
    const float* tb = (const float*)d_in[2];
    const float* pw = (const float*)d_in[3];
    const float* pb = (const float*)d_in[4];
    const float* gw = (const float*)d_in[5];
    const float* gb = (const float*)d_in[6];
    const float* ww = (const float*)d_in[7];
    const float* wb = (const float*)d_in[8];
    float* out = (float*)d_out;

    (void)in_sizes; (void)n_in; (void)out_size;

    proj_kernel<<<dim3(NTOK / 128, BATCH, 3), 256>>>(x, tw, tb, pw, pb, gw, gb);

    const int flash_smem = (64 * 132 + 64 * 132 + 64 * 128 + 64 * 64) * (int)sizeof(float);
    cudaFuncSetAttribute(flash_kernel,
                         cudaFuncAttributeMaxDynamicSharedMemorySize, flash_smem);
    flash_kernel<<<dim3(NTOK / 64, BATCH), 256, flash_smem>>>();

    out_kernel<<<dim3(NTOK / 128, CIN / 128, BATCH), 256>>>(ww, wb, out);
}

// round 5
// speedup vs baseline: 3.2273x; 3.2270x over previous
#include <cuda_runtime.h>
#include <cuda_bf16.h>
#include <cstdint>
#include <math.h>

#define BATCH 8
#define CIN   256
#define NTOK  4096
#define CD    128
#define NKT   64

// ---------------- device scratch ----------------
__device__ __nv_bfloat16 g_Qh[BATCH * NTOK * CD];
__device__ __nv_bfloat16 g_Ql[BATCH * NTOK * CD];
__device__ __nv_bfloat16 g_Kh[BATCH * NTOK * CD];
__device__ __nv_bfloat16 g_Kl[BATCH * NTOK * CD];
__device__ __nv_bfloat16 g_Vh[BATCH * NTOK * CD];
__device__ __nv_bfloat16 g_Vl[BATCH * NTOK * CD];
__device__ float g_Y[BATCH * NTOK * CD];

// ---------------- helpers ----------------
__device__ __forceinline__ uint32_t s2u(const void* p) {
    uint32_t a;
    asm("{ .reg .u64 t; cvta.to.shared.u64 t, %1; cvt.u32.u64 %0, t; }"
        : "=r"(a) : "l"(p));
    return a;
}
__device__ __forceinline__ void ldsm4(uint32_t* r, uint32_t a) {
    asm volatile("ldmatrix.sync.aligned.m8n8.x4.shared.b16 {%0,%1,%2,%3}, [%4];"
        : "=r"(r[0]), "=r"(r[1]), "=r"(r[2]), "=r"(r[3]) : "r"(a));
}
__device__ __forceinline__ void ldsm4t(uint32_t* r, uint32_t a) {
    asm volatile("ldmatrix.sync.aligned.m8n8.x4.trans.shared.b16 {%0,%1,%2,%3}, [%4];"
        : "=r"(r[0]), "=r"(r[1]), "=r"(r[2]), "=r"(r[3]) : "r"(a));
}
__device__ __forceinline__ void mma16816(float* d, const uint32_t* a, const uint32_t* b) {
    asm volatile(
        "mma.sync.aligned.m16n8k16.row.col.f32.bf16.bf16.f32 "
        "{%0,%1,%2,%3},{%4,%5,%6,%7},{%8,%9},{%0,%1,%2,%3};"
        : "+f"(d[0]), "+f"(d[1]), "+f"(d[2]), "+f"(d[3])
        : "r"(a[0]), "r"(a[1]), "r"(a[2]), "r"(a[3]), "r"(b[0]), "r"(b[1]));
}
__device__ __forceinline__ void cp16(uint32_t dst, const void* src) {
    asm volatile("cp.async.cg.shared.global [%0], [%1], 16;" :: "r"(dst), "l"(src));
}
__device__ __forceinline__ void cp_commit() { asm volatile("cp.async.commit_group;"); }
__device__ __forceinline__ void cp_wait1() { asm volatile("cp.async.wait_group 1;" ::: "memory"); }
__device__ __forceinline__ void cp_wait0() { asm volatile("cp.async.wait_group 0;" ::: "memory"); }

// smem tile: rows of 128 bf16 (256B), 16B chunks XOR-swizzled
__device__ __forceinline__ uint32_t swz(int r, int c16) {
    return (uint32_t)(r * 256 + ((c16 ^ (r & 7)) << 4));
}

// exp on the FMA pipe
__device__ __forceinline__ float fexp(float x) {
    float z = fmaxf(x * 1.4426950408889634f, -126.f);
    float r = z + 12582912.f;
    int ni = __float_as_int(r) - 0x4B400000;
    float f = z - (r - 12582912.f);
    float u = f * 0.6931471805599453f;
    float e = 1.9841269841e-4f;
    e = fmaf(e, u, 1.3888888889e-3f);
    e = fmaf(e, u, 8.3333333333e-3f);
    e = fmaf(e, u, 4.1666666667e-2f);
    e = fmaf(e, u, 1.6666666667e-1f);
    e = fmaf(e, u, 0.5f);
    e = fmaf(e, u, 1.0f);
    e = fmaf(e, u, 1.0f);
    return e * __int_as_float((ni + 127) << 23);
}

__device__ __forceinline__ void bfsplit(float v, unsigned short& h, unsigned short& l) {
    __nv_bfloat16 bh = __float2bfloat16_rn(v);
    __nv_bfloat16 bl = __float2bfloat16_rn(v - __bfloat162float(bh));
    h = __bfloat16_as_ushort(bh);
    l = __bfloat16_as_ushort(bl);
}
// pack two floats to bf16x2 (hi) and residual bf16x2 (lo)
__device__ __forceinline__ void split2(float x, float y, uint32_t& h, uint32_t& l) {
    unsigned short hx, lx, hy, ly;
    bfsplit(x, hx, lx);
    bfsplit(y, hy, ly);
    h = (uint32_t)hx | ((uint32_t)hy << 16);
    l = (uint32_t)lx | ((uint32_t)ly << 16);
}

// ---------------------------------------------------------------------------
// Projections -> bf16 hi/lo, all [b][n][128]
// ---------------------------------------------------------------------------
__global__ __launch_bounds__(256) void proj_kernel(
    const float* __restrict__ x,
    const float* __restrict__ tw, const float* __restrict__ tb,
    const float* __restrict__ pw, const float* __restrict__ pb,
    const float* __restrict__ gw, const float* __restrict__ gb)
{
    const int b     = blockIdx.y;
    const int which = blockIdx.z;
    const float* w; const float* bias;
    __nv_bfloat16* oh; __nv_bfloat16* ol;
    if (which == 0)      { w = tw; bias = tb; oh = g_Qh; ol = g_Ql; }
    else if (which == 1) { w = pw; bias = pb; oh = g_Kh; ol = g_Kl; }
    else                 { w = gw; bias = gb; oh = g_Vh; ol = g_Vl; }
    oh += (size_t)b * NTOK * CD;
    ol += (size_t)b * NTOK * CD;
    const float* xb = x + (size_t)b * CIN * NTOK;
    const int n0 = blockIdx.x * 128;

    __shared__ float As[16][128];
    __shared__ float Bs[16][128];

    const int t  = threadIdx.x;
    const int ty = t >> 4;
    const int tx = t & 15;

    float acc[8][8];
    #pragma unroll
    for (int i = 0; i < 8; i++)
        #pragma unroll
        for (int j = 0; j < 8; j++) acc[i][j] = 0.f;

    for (int c0 = 0; c0 < CIN; c0 += 16) {
        #pragma unroll
        for (int r = 0; r < 2; r++) {
            int idx = t + r * 256;
            int cc  = idx >> 5;
            int n4  = (idx & 31) << 2;
            *(float4*)&As[cc][n4] =
                *(const float4*)&xb[(size_t)(c0 + cc) * NTOK + n0 + n4];
        }
        {
            int k  = t & 127;
            int cg = (t >> 7) << 3;
            float4 w0 = *(const float4*)&w[(size_t)k * CIN + c0 + cg];
            float4 w1 = *(const float4*)&w[(size_t)k * CIN + c0 + cg + 4];
            Bs[cg + 0][k] = w0.x; Bs[cg + 1][k] = w0.y;
            Bs[cg + 2][k] = w0.z; Bs[cg + 3][k] = w0.w;
            Bs[cg + 4][k] = w1.x; Bs[cg + 5][k] = w1.y;
            Bs[cg + 6][k] = w1.z; Bs[cg + 7][k] = w1.w;
        }
        __syncthreads();
        #pragma unroll
        for (int cc = 0; cc < 16; cc++) {
            float a[8], bb[8];
            *(float4*)&a[0]  = *(const float4*)&As[cc][ty * 8];
            *(float4*)&a[4]  = *(const float4*)&As[cc][ty * 8 + 4];
            *(float4*)&bb[0] = *(const float4*)&Bs[cc][tx * 4];
            *(float4*)&bb[4] = *(const float4*)&Bs[cc][64 + tx * 4];
            #pragma unroll
            for (int i = 0; i < 8; i++)
                #pragma unroll
                for (int j = 0; j < 8; j++)
                    acc[i][j] = fmaf(a[i], bb[j], acc[i][j]);
        }
        __syncthreads();
    }

    float b0[4], b1[4];
    #pragma unroll
    for (int j = 0; j < 4; j++) {
        b0[j] = bias[tx * 4 + j];
        b1[j] = bias[64 + tx * 4 + j];
    }
    #pragma unroll
    for (int i = 0; i < 8; i++) {
        size_t row = (size_t)(n0 + ty * 8 + i);
        unsigned short hs[8], ls[8];
        #pragma unroll
        for (int j = 0; j < 4; j++) bfsplit(acc[i][j] + b0[j], hs[j], ls[j]);
        #pragma unroll
        for (int j = 4; j < 8; j++) bfsplit(acc[i][j] + b1[j - 4], hs[j], ls[j]);
        *(uint2*)&oh[row * CD + tx * 4] =
            make_uint2((unsigned)hs[0] | ((unsigned)hs[1] << 16),
                       (unsigned)hs[2] | ((unsigned)hs[3] << 16));
        *(uint2*)&oh[row * CD + 64 + tx * 4] =
            make_uint2((unsigned)hs[4] | ((unsigned)hs[5] << 16),
                       (unsigned)hs[6] | ((unsigned)hs[7] << 16));
        *(uint2*)&ol[row * CD + tx * 4] =
            make_uint2((unsigned)ls[0] | ((unsigned)ls[1] << 16),
                       (unsigned)ls[2] | ((unsigned)ls[3] << 16));
        *(uint2*)&ol[row * CD + 64 + tx * 4] =
            make_uint2((unsigned)ls[4] | ((unsigned)ls[5] << 16),
                       (unsigned)ls[6] | ((unsigned)ls[7] << 16));
    }
}

// ---------------------------------------------------------------------------
// HMMA flash attention. BQ=128, BK=64. grid (32, 8), 256 threads (8 warps).
// Warp w owns q-rows [w*16, w*16+16).
// smem: QH 0, QL 32K | K hi 2 stages @64K, K lo @96K | V hi @128K, V lo @160K
// ---------------------------------------------------------------------------
#define S_QH 0u
#define S_QL 32768u
#define S_KH 65536u
#define S_KL 98304u
#define S_VH 131072u
#define S_VL 163840u
#define S_STAGE 16384u
#define SMEM_FLASH 196608u

__global__ __launch_bounds__(256, 1) void flash_mma_kernel()
{
    extern __shared__ __align__(256) char sm[];
    const uint32_t su = s2u(sm);

    const int t    = threadIdx.x;
    const int w    = t >> 5;
    const int lane = t & 31;
    const int sub    = lane >> 3;   // ldmatrix sub-matrix id
    const int rowInM = lane & 7;
    const int b  = blockIdx.y;
    const int q0 = blockIdx.x * 128;

    const __nv_bfloat16* Qhg = g_Qh + ((size_t)b * NTOK + q0) * CD;
    const __nv_bfloat16* Qlg = g_Ql + ((size_t)b * NTOK + q0) * CD;
    const __nv_bfloat16* Khg = g_Kh + (size_t)b * NTOK * CD;
    const __nv_bfloat16* Klg = g_Kl + (size_t)b * NTOK * CD;
    const __nv_bfloat16* Vhg = g_Vh + (size_t)b * NTOK * CD;
    const __nv_bfloat16* Vlg = g_Vl + (size_t)b * NTOK * CD;

    // Q tile (hi+lo), 128 rows x 16 chunks
    for (int i = t; i < 2048; i += 256) {
        int r = i >> 4, c = i & 15;
        uint32_t off = swz(r, c);
        cp16(su + S_QH + off, Qhg + (size_t)r * CD + c * 8);
        cp16(su + S_QL + off, Qlg + (size_t)r * CD + c * 8);
    }
    // prefetch kt=0
    {
        const __nv_bfloat16 *kh = Khg, *kl = Klg, *vh = Vhg, *vl = Vlg;
        for (int i = t; i < 1024; i += 256) {
            int r = i >> 4, c = i & 15;
            uint32_t off = swz(r, c);
            cp16(su + S_KH + off, kh + (size_t)r * CD + c * 8);
            cp16(su + S_KL + off, kl + (size_t)r * CD + c * 8);
            cp16(su + S_VH + off, vh + (size_t)r * CD + c * 8);
            cp16(su + S_VL + off, vl + (size_t)r * CD + c * 8);
        }
    }
    cp_commit();

    float o[16][4];
    #pragma unroll
    for (int f = 0; f < 16; f++)
        #pragma unroll
        for (int j = 0; j < 4; j++) o[f][j] = 0.f;
    float m0 = -1e30f, m1 = -1e30f, l0 = 0.f, l1 = 0.f;

    for (int kt = 0; kt < NKT; kt++) {
        const uint32_t st = (kt & 1) * S_STAGE;
        if (kt + 1 < NKT) {
            const uint32_t st2 = ((kt + 1) & 1) * S_STAGE;
            const size_t gofs = (size_t)(kt + 1) * 64 * CD;
            for (int i = t; i < 1024; i += 256) {
                int r = i >> 4, c = i & 15;
                uint32_t off = swz(r, c) + st2;
                size_t g = gofs + (size_t)r * CD + c * 8;
                cp16(su + S_KH + off, Khg + g);
                cp16(su + S_KL + off, Klg + g);
                cp16(su + S_VH + off, Vhg + g);
                cp16(su + S_VL + off, Vlg + g);
            }
            cp_commit();
            cp_wait1();
        } else {
            cp_wait0();
        }
        __syncthreads();

        // ---------- S = Q K^T (3 split products) ----------
        float s[8][4];
        #pragma unroll
        for (int f = 0; f < 8; f++)
            #pragma unroll
            for (int j = 0; j < 4; j++) s[f][j] = 0.f;

        #pragma unroll
        for (int kc = 0; kc < 8; kc++) {
            uint32_t qh[4], ql[4];
            {
                int row = w * 16 + rowInM + ((sub & 1) << 3);
                int c16 = kc * 2 + (sub >> 1);
                ldsm4(qh, su + S_QH + swz(row, c16));
                ldsm4(ql, su + S_QL + swz(row, c16));
            }
            #pragma unroll
            for (int nb = 0; nb < 4; nb++) {
                uint32_t kh4[4], kl4[4];
                int row = nb * 16 + rowInM + ((sub >> 1) << 3);
                int c16 = kc * 2 + (sub & 1);
                ldsm4(kh4, su + S_KH + st + swz(row, c16));
                ldsm4(kl4, su + S_KL + st + swz(row, c16));
                mma16816(s[nb * 2],     qh, kh4);
                mma16816(s[nb * 2 + 1], qh, kh4 + 2);
                mma16816(s[nb * 2],     qh, kl4);
                mma16816(s[nb * 2 + 1], qh, kl4 + 2);
                mma16816(s[nb * 2],     ql, kh4);
                mma16816(s[nb * 2 + 1], ql, kh4 + 2);
            }
        }

        // ---------- online softmax (rows: g=lane>>2 and g+8) ----------
        float mx0 = -1e30f, mx1 = -1e30f;
        #pragma unroll
        for (int f = 0; f < 8; f++) {
            mx0 = fmaxf(mx0, fmaxf(s[f][0], s[f][1]));
            mx1 = fmaxf(mx1, fmaxf(s[f][2], s[f][3]));
        }
        mx0 = fmaxf(mx0, __shfl_xor_sync(0xffffffffu, mx0, 1));
        mx0 = fmaxf(mx0, __shfl_xor_sync(0xffffffffu, mx0, 2));
        mx1 = fmaxf(mx1, __shfl_xor_sync(0xffffffffu, mx1, 1));
        mx1 = fmaxf(mx1, __shfl_xor_sync(0xffffffffu, mx1, 2));
        float mn0 = fmaxf(m0, mx0), mn1 = fmaxf(m1, mx1);
        float c0 = fexp(m0 - mn0), c1 = fexp(m1 - mn1);
        m0 = mn0; m1 = mn1;

        uint32_t ph0[8], ph1[8], pl0[8], pl1[8];
        float ps0 = 0.f, ps1 = 0.f;
        #pragma unroll
        for (int f = 0; f < 8; f++) {
            float p00 = fexp(s[f][0] - m0);
            float p01 = fexp(s[f][1] - m0);
            float p10 = fexp(s[f][2] - m1);
            float p11 = fexp(s[f][3] - m1);
            ps0 += p00 + p01;
            ps1 += p10 + p11;
            split2(p00, p01, ph0[f], pl0[f]);
            split2(p10, p11, ph1[f], pl1[f]);
        }
        ps0 += __shfl_xor_sync(0xffffffffu, ps0, 1);
        ps0 += __shfl_xor_sync(0xffffffffu, ps0, 2);
        ps1 += __shfl_xor_sync(0xffffffffu, ps1, 1);
        ps1 += __shfl_xor_sync(0xffffffffu, ps1, 2);
        l0 = l0 * c0 + ps0;
        l1 = l1 * c1 + ps1;
        #pragma unroll
        for (int f = 0; f < 16; f++) {
            o[f][0] *= c0; o[f][1] *= c0;
            o[f][2] *= c1; o[f][3] *= c1;
        }

        // ---------- O += P V (3 split products) ----------
        #pragma unroll
        for (int kc = 0; kc < 4; kc++) {
            uint32_t ah[4] = {ph0[kc * 2], ph1[kc * 2], ph0[kc * 2 + 1], ph1[kc * 2 + 1]};
            uint32_t al[4] = {pl0[kc * 2], pl1[kc * 2], pl0[kc * 2 + 1], pl1[kc * 2 + 1]};
            int row = kc * 16 + rowInM + ((sub & 1) << 3);
            #pragma unroll
            for (int vb = 0; vb < 8; vb++) {
                int c16 = vb * 2 + (sub >> 1);
                uint32_t vh4[4], vl4[4];
                ldsm4t(vh4, su + S_VH + st + swz(row, c16));
                ldsm4t(vl4, su + S_VL + st + swz(row, c16));
                mma16816(o[vb * 2],     ah, vh4);
                mma16816(o[vb * 2 + 1], ah, vh4 + 2);
                mma16816(o[vb * 2],     ah, vl4);
                mma16816(o[vb * 2 + 1], ah, vl4 + 2);
                mma16816(o[vb * 2],     al, vh4);
                mma16816(o[vb * 2 + 1], al, vh4 + 2);
            }
        }
        __syncthreads();  // protect stage buffers before next prefetch overwrite
    }

    // ---------- normalize + store ----------
    const float i0 = 1.f / l0, i1 = 1.f / l1;
    const int g   = lane >> 2;
    const int tid = lane & 3;
    float* Y0 = g_Y + ((size_t)b * NTOK + q0 + w * 16 + g) * CD;
    float* Y1 = Y0 + 8 * CD;
    #pragma unroll
    for (int f = 0; f < 16; f++) {
        int col = f * 8 + tid * 2;
        float2 r0 = make_float2(o[f][0] * i0, o[f][1] * i0);
        float2 r1 = make_float2(o[f][2] * i1, o[f][3] * i1);
        *(float2*)&Y0[col] = r0;
        *(float2*)&Y1[col] = r1;
    }
}

// ---------------------------------------------------------------------------
// Output conv: out[b,c,n] = sum_v Y[b,n,v] * w_w[c,v] + w_b[c]
// ---------------------------------------------------------------------------
__global__ __launch_bounds__(256) void out_kernel(
    const float* __restrict__ ww, const float* __restrict__ wb,
    float* __restrict__ out)
{
    const int b  = blockIdx.z;
    const int c0 = blockIdx.y * 128;
    const int n0 = blockIdx.x * 128;

    __shared__ float Ws[16][128];
    __shared__ float Ys[16][128];

    const float* Yb = g_Y + (size_t)b * NTOK * CD;
    float* ob = out + (size_t)b * CIN * NTOK;

    const int t  = threadIdx.x;
    const int ty = t >> 4;
    const int tx = t & 15;

    float acc[8][8];
    #pragma unroll
    for (int i = 0; i < 8; i++)
        #pragma unroll
        for (int j = 0; j < 8; j++) acc[i][j] = 0.f;

    for (int v0 = 0; v0 < CD; v0 += 16) {
        {
            int cn = t >> 1;
            int vg = (t & 1) << 3;
            float4 w0 = *(const float4*)&ww[(size_t)(c0 + cn) * CD + v0 + vg];
            float4 w1 = *(const float4*)&ww[(size_t)(c0 + cn) * CD + v0 + vg + 4];
            Ws[vg + 0][cn] = w0.x; Ws[vg + 1][cn] = w0.y;
            Ws[vg + 2][cn] = w0.z; Ws[vg + 3][cn] = w0.w;
            Ws[vg + 4][cn] = w1.x; Ws[vg + 5][cn] = w1.y;
            Ws[vg + 6][cn] = w1.z; Ws[vg + 7][cn] = w1.w;
            float4 y0 = *(const float4*)&Yb[(size_t)(n0 + cn) * CD + v0 + vg];
            float4 y1 = *(const float4*)&Yb[(size_t)(n0 + cn) * CD + v0 + vg + 4];
            Ys[vg + 0][cn] = y0.x; Ys[vg + 1][cn] = y0.y;
            Ys[vg + 2][cn] = y0.z; Ys[vg + 3][cn] = y0.w;
            Ys[vg + 4][cn] = y1.x; Ys[vg + 5][cn] = y1.y;
            Ys[vg + 6][cn] = y1.z; Ys[vg + 7][cn] = y1.w;
        }
        __syncthreads();
        #pragma unroll
        for (int vv = 0; vv < 16; vv++) {
            float a[8], bb[8];
            *(float4*)&a[0]  = *(const float4*)&Ws[vv][ty * 8];
            *(float4*)&a[4]  = *(const float4*)&Ws[vv][ty * 8 + 4];
            *(float4*)&bb[0] = *(const float4*)&Ys[vv][tx * 4];
            *(float4*)&bb[4] = *(const float4*)&Ys[vv][64 + tx * 4];
            #pragma unroll
            for (int i = 0; i < 8; i++)
                #pragma unroll
                for (int j = 0; j < 8; j++)
                    acc[i][j] = fmaf(a[i], bb[j], acc[i][j]);
        }
        __syncthreads();
    }

    #pragma unroll
    for (int i = 0; i < 8; i++) {
        int c = c0 + ty * 8 + i;
        float bv = wb[c];
        float4 r0 = make_float4(acc[i][0] + bv, acc[i][1] + bv,
                                acc[i][2] + bv, acc[i][3] + bv);
        float4 r1 = make_float4(acc[i][4] + bv, acc[i][5] + bv,
                                acc[i][6] + bv, acc[i][7] + bv);
        *(float4*)&ob[(size_t)c * NTOK + n0 + tx * 4]      = r0;
        *(float4*)&ob[(size_t)c * NTOK + n0 + 64 + tx * 4] = r1;
    }
}

// ---------------------------------------------------------------------------
extern "C" void kernel_launch(void* const* d_in, const int* in_sizes, int n_in,
                              void* d_out, int out_size)
{
    const float* x  = (const float*)d_in[0];
    const float* tw = (const float*)d_in[1];
    const float* tb = (const float*)d_in[2];
    const float* pw = (const float*)d_in[3];
    const float* pb = (const float*)d_in[4];
    const float* gw = (const float*)d_in[5];
    const float* gb = (const float*)d_in[6];
    const float* ww = (const float*)d_in[7];
    const float* wb = (const float*)d_in[8];
    float* out = (float*)d_out;
    (void)in_sizes; (void)n_in; (void)out_size;

    proj_kernel<<<dim3(NTOK / 128, BATCH, 3), 256>>>(x, tw, tb, pw, pb, gw, gb);

    cudaFuncSetAttribute(flash_mma_kernel,
                         cudaFuncAttributeMaxDynamicSharedMemorySize, SMEM_FLASH);
    flash_mma_kernel<<<dim3(NTOK / 128, BATCH), 256, SMEM_FLASH>>>();

    out_kernel<<<dim3(NTOK / 128, CIN / 128, BATCH), 256>>>(ww, wb, out);
}

// round 7
// speedup vs baseline: 4.2750x; 1.3246x over previous
#include <cuda_runtime.h>
#include <cuda_bf16.h>
#include <cuda_fp16.h>
#include <cstdint>
#include <math.h>

#define BATCH 8
#define CIN   256
#define NTOK  4096
#define CD    128
#define NKT   64

// ---------------- device scratch ----------------
__device__ __nv_bfloat16 g_Xh[BATCH * CIN * NTOK];
__device__ __nv_bfloat16 g_Xl[BATCH * CIN * NTOK];
__device__ __nv_bfloat16 g_Twh[CD * CIN], g_Twl[CD * CIN];
__device__ __nv_bfloat16 g_Pwh[CD * CIN], g_Pwl[CD * CIN];
__device__ __nv_bfloat16 g_Gwh[CD * CIN], g_Gwl[CD * CIN];
__device__ __nv_bfloat16 g_Wwh[CIN * CD], g_Wwl[CIN * CD];
__device__ __nv_bfloat16 g_Qh[BATCH * NTOK * CD], g_Ql[BATCH * NTOK * CD];
__device__ __nv_bfloat16 g_Kh[BATCH * NTOK * CD], g_Kl[BATCH * NTOK * CD];
__device__ __half        g_Vh[BATCH * NTOK * CD], g_Vl[BATCH * NTOK * CD];
__device__ __nv_bfloat16 g_Yh[BATCH * NTOK * CD], g_Yl[BATCH * NTOK * CD];

// ---------------- helpers ----------------
__device__ __forceinline__ uint32_t s2u(const void* p) {
    uint32_t a;
    asm("{ .reg .u64 t; cvta.to.shared.u64 t, %1; cvt.u32.u64 %0, t; }"
        : "=r"(a) : "l"(p));
    return a;
}
__device__ __forceinline__ void ldsm4(uint32_t* r, uint32_t a) {
    asm volatile("ldmatrix.sync.aligned.m8n8.x4.shared.b16 {%0,%1,%2,%3}, [%4];"
        : "=r"(r[0]), "=r"(r[1]), "=r"(r[2]), "=r"(r[3]) : "r"(a));
}
__device__ __forceinline__ void ldsm4t(uint32_t* r, uint32_t a) {
    asm volatile("ldmatrix.sync.aligned.m8n8.x4.trans.shared.b16 {%0,%1,%2,%3}, [%4];"
        : "=r"(r[0]), "=r"(r[1]), "=r"(r[2]), "=r"(r[3]) : "r"(a));
}
__device__ __forceinline__ void mma_bf(float* d, const uint32_t* a, uint32_t b0, uint32_t b1) {
    asm volatile(
        "mma.sync.aligned.m16n8k16.row.col.f32.bf16.bf16.f32 "
        "{%0,%1,%2,%3},{%4,%5,%6,%7},{%8,%9},{%0,%1,%2,%3};"
        : "+f"(d[0]), "+f"(d[1]), "+f"(d[2]), "+f"(d[3])
        : "r"(a[0]), "r"(a[1]), "r"(a[2]), "r"(a[3]), "r"(b0), "r"(b1));
}
__device__ __forceinline__ void mma_hf(float* d, const uint32_t* a, uint32_t b0, uint32_t b1) {
    asm volatile(
        "mma.sync.aligned.m16n8k16.row.col.f32.f16.f16.f32 "
        "{%0,%1,%2,%3},{%4,%5,%6,%7},{%8,%9},{%0,%1,%2,%3};"
        : "+f"(d[0]), "+f"(d[1]), "+f"(d[2]), "+f"(d[3])
        : "r"(a[0]), "r"(a[1]), "r"(a[2]), "r"(a[3]), "r"(b0), "r"(b1));
}
__device__ __forceinline__ void cp16(uint32_t dst, const void* src) {
    asm volatile("cp.async.cg.shared.global [%0], [%1], 16;" :: "r"(dst), "l"(src));
}
__device__ __forceinline__ void cp_commit() { asm volatile("cp.async.commit_group;"); }
__device__ __forceinline__ void cp_wait1() { asm volatile("cp.async.wait_group 1;" ::: "memory"); }
__device__ __forceinline__ void cp_wait0() { asm volatile("cp.async.wait_group 0;" ::: "memory"); }

// 256B-row swizzle (16 chunks of 16B) and 128B-row swizzle (8 chunks)
__device__ __forceinline__ uint32_t swz(int r, int c16) {
    return (uint32_t)(r * 256 + ((c16 ^ (r & 7)) << 4));
}
__device__ __forceinline__ uint32_t swzB(int r, int c16) {
    return (uint32_t)(r * 128 + ((c16 ^ (r & 7)) << 4));
}

// exp on the FMA pipe
__device__ __forceinline__ float fexp(float x) {
    float z = fmaxf(x * 1.4426950408889634f, -126.f);
    float r = z + 12582912.f;
    int ni = __float_as_int(r) - 0x4B400000;
    float f = z - (r - 12582912.f);
    float u = f * 0.6931471805599453f;
    float e = 1.9841269841e-4f;
    e = fmaf(e, u, 1.3888888889e-3f);
    e = fmaf(e, u, 8.3333333333e-3f);
    e = fmaf(e, u, 4.1666666667e-2f);
    e = fmaf(e, u, 1.6666666667e-1f);
    e = fmaf(e, u, 0.5f);
    e = fmaf(e, u, 1.0f);
    e = fmaf(e, u, 1.0f);
    return e * __int_as_float((ni + 127) << 23);
}

__device__ __forceinline__ void bfsplit(float v, unsigned short& h, unsigned short& l) {
    __nv_bfloat16 bh = __float2bfloat16_rn(v);
    __nv_bfloat16 bl = __float2bfloat16_rn(v - __bfloat162float(bh));
    h = __bfloat16_as_ushort(bh);
    l = __bfloat16_as_ushort(bl);
}
__device__ __forceinline__ void split2(float x, float y, uint32_t& h, uint32_t& l) {
    unsigned short hx, lx, hy, ly;
    bfsplit(x, hx, lx);
    bfsplit(y, hy, ly);
    h = (uint32_t)hx | ((uint32_t)hy << 16);
    l = (uint32_t)lx | ((uint32_t)ly << 16);
}
__device__ __forceinline__ void hsplit2(float x, float y, uint32_t& h, uint32_t& l) {
    __half hx = __float2half_rn(x), hy = __float2half_rn(y);
    __half lx = __float2half_rn(x - __half2float(hx));
    __half ly = __float2half_rn(y - __half2float(hy));
    h = (uint32_t)__half_as_ushort(hx) | ((uint32_t)__half_as_ushort(hy) << 16);
    l = (uint32_t)__half_as_ushort(lx) | ((uint32_t)__half_as_ushort(ly) << 16);
}
// pack (lo_elem, hi_elem) -> f16x2
__device__ __forceinline__ uint32_t pack_h2(float lo, float hi) {
    uint32_t r;
    asm("cvt.rn.f16x2.f32 %0, %1, %2;" : "=r"(r) : "f"(hi), "f"(lo));
    return r;
}

// ---------------------------------------------------------------------------
// conversion passes: x -> bf16 hi/lo, weights -> bf16 hi/lo
// ---------------------------------------------------------------------------
__global__ __launch_bounds__(256) void conv_x_kernel(const float* __restrict__ x)
{
    size_t i = ((size_t)blockIdx.x * 256 + threadIdx.x) * 4;
    float4 v = *(const float4*)&x[i];
    unsigned short h[4], l[4];
    bfsplit(v.x, h[0], l[0]); bfsplit(v.y, h[1], l[1]);
    bfsplit(v.z, h[2], l[2]); bfsplit(v.w, h[3], l[3]);
    *(uint2*)&g_Xh[i] = make_uint2((unsigned)h[0] | ((unsigned)h[1] << 16),
                                   (unsigned)h[2] | ((unsigned)h[3] << 16));
    *(uint2*)&g_Xl[i] = make_uint2((unsigned)l[0] | ((unsigned)l[1] << 16),
                                   (unsigned)l[2] | ((unsigned)l[3] << 16));
}

__global__ __launch_bounds__(256) void conv_w_kernel(
    const float* __restrict__ tw, const float* __restrict__ pw,
    const float* __restrict__ gw, const float* __restrict__ ww)
{
    const float* src; __nv_bfloat16* dh; __nv_bfloat16* dl;
    switch (blockIdx.y) {
        case 0: src = tw; dh = g_Twh; dl = g_Twl; break;
        case 1: src = pw; dh = g_Pwh; dl = g_Pwl; break;
        case 2: src = gw; dh = g_Gwh; dl = g_Gwl; break;
        default: src = ww; dh = g_Wwh; dl = g_Wwl; break;
    }
    size_t i = ((size_t)blockIdx.x * 256 + threadIdx.x) * 4;
    float4 v = *(const float4*)&src[i];
    unsigned short h[4], l[4];
    bfsplit(v.x, h[0], l[0]); bfsplit(v.y, h[1], l[1]);
    bfsplit(v.z, h[2], l[2]); bfsplit(v.w, h[3], l[3]);
    *(uint2*)&dh[i] = make_uint2((unsigned)h[0] | ((unsigned)h[1] << 16),
                                 (unsigned)h[2] | ((unsigned)h[3] << 16));
    *(uint2*)&dl[i] = make_uint2((unsigned)l[0] | ((unsigned)l[1] << 16),
                                 (unsigned)l[2] | ((unsigned)l[3] << 16));
}

// ---------------------------------------------------------------------------
// HMMA projections: D[n][k] = sum_c x[c][n]*w[k][c] + bias.  grid (32,8,3).
// smem per stage: XH/XL [64c][128n] (256B rows), WH/WL [128k][64c] (128B rows)
// ---------------------------------------------------------------------------
#define PS_XH(s) ((s) * 65536u)
#define PS_XL(s) ((s) * 65536u + 16384u)
#define PS_WH(s) ((s) * 65536u + 32768u)
#define PS_WL(s) ((s) * 65536u + 49152u)
#define SMEM_PROJ 131072u

__global__ __launch_bounds__(256, 1) void proj_mma_kernel(
    const float* __restrict__ tb, const float* __restrict__ pb,
    const float* __restrict__ gb)
{
    extern __shared__ __align__(256) char sm[];
    const uint32_t su = s2u(sm);

    const int t = threadIdx.x;
    const int w = t >> 5;
    const int lane = t & 31;
    const int sub = lane >> 3;
    const int rowInM = lane & 7;
    const int b = blockIdx.y;
    const int which = blockIdx.z;
    const int n0 = blockIdx.x * 128;

    const __nv_bfloat16 *wh, *wl; const float* bias;
    if (which == 0)      { wh = g_Twh; wl = g_Twl; bias = tb; }
    else if (which == 1) { wh = g_Pwh; wl = g_Pwl; bias = pb; }
    else                 { wh = g_Gwh; wl = g_Gwl; bias = gb; }
    const __nv_bfloat16* xh = g_Xh + (size_t)b * CIN * NTOK;
    const __nv_bfloat16* xl = g_Xl + (size_t)b * CIN * NTOK;

    auto load_stage = [&](int c0, int s) {
        for (int i = t; i < 1024; i += 256) {
            int r = i >> 4, ch = i & 15;
            uint32_t off = swz(r, ch);
            size_t g = (size_t)(c0 + r) * NTOK + n0 + ch * 8;
            cp16(su + PS_XH(s) + off, xh + g);
            cp16(su + PS_XL(s) + off, xl + g);
        }
        for (int i = t; i < 1024; i += 256) {
            int r = i >> 3, ch = i & 7;
            uint32_t off = swzB(r, ch);
            size_t g = (size_t)r * CIN + c0 + ch * 8;
            cp16(su + PS_WH(s) + off, wh + g);
            cp16(su + PS_WL(s) + off, wl + g);
        }
    };

    float d[16][4];
    #pragma unroll
    for (int i = 0; i < 16; i++)
        #pragma unroll
        for (int j = 0; j < 4; j++) d[i][j] = 0.f;

    load_stage(0, 0);
    cp_commit();

    for (int ck = 0; ck < 4; ck++) {
        if (ck < 3) { load_stage((ck + 1) * 64, (ck + 1) & 1); cp_commit(); cp_wait1(); }
        else cp_wait0();
        __syncthreads();
        const int s = ck & 1;
        #pragma unroll
        for (int kc = 0; kc < 4; kc++) {
            uint32_t ah[4], al[4];
            {
                int row = kc * 16 + rowInM + ((sub >> 1) << 3);
                int c16 = w * 2 + (sub & 1);
                ldsm4t(ah, su + PS_XH(s) + swz(row, c16));
                ldsm4t(al, su + PS_XL(s) + swz(row, c16));
            }
            #pragma unroll
            for (int nbp = 0; nbp < 8; nbp++) {
                uint32_t bh[4], bl[4];
                int row = nbp * 16 + rowInM + ((sub >> 1) << 3);
                int c16 = kc * 2 + (sub & 1);
                ldsm4(bh, su + PS_WH(s) + swzB(row, c16));
                ldsm4(bl, su + PS_WL(s) + swzB(row, c16));
                mma_bf(d[nbp * 2],     ah, bh[0], bh[1]);
                mma_bf(d[nbp * 2],     ah, bl[0], bl[1]);
                mma_bf(d[nbp * 2],     al, bh[0], bh[1]);
                mma_bf(d[nbp * 2 + 1], ah, bh[2], bh[3]);
                mma_bf(d[nbp * 2 + 1], ah, bl[2], bl[3]);
                mma_bf(d[nbp * 2 + 1], al, bh[2], bh[3]);
            }
        }
        __syncthreads();
    }

    // epilogue
    const int g = lane >> 2, tq = lane & 3;
    const size_t nlo = (size_t)(n0 + w * 16 + g);
    const size_t nhi = nlo + 8;
    if (which < 2) {
        __nv_bfloat16* oh = (which == 0 ? g_Qh : g_Kh) + (size_t)b * NTOK * CD;
        __nv_bfloat16* ol = (which == 0 ? g_Ql : g_Kl) + (size_t)b * NTOK * CD;
        #pragma unroll
        for (int nb = 0; nb < 16; nb++) {
            int k0 = nb * 8 + tq * 2;
            float2 bb = *(const float2*)&bias[k0];
            uint32_t h, l;
            split2(d[nb][0] + bb.x, d[nb][1] + bb.y, h, l);
            *(uint32_t*)&oh[nlo * CD + k0] = h;
            *(uint32_t*)&ol[nlo * CD + k0] = l;
            split2(d[nb][2] + bb.x, d[nb][3] + bb.y, h, l);
            *(uint32_t*)&oh[nhi * CD + k0] = h;
            *(uint32_t*)&ol[nhi * CD + k0] = l;
        }
    } else {
        __half* oh = g_Vh + (size_t)b * NTOK * CD;
        __half* ol = g_Vl + (size_t)b * NTOK * CD;
        #pragma unroll
        for (int nb = 0; nb < 16; nb++) {
            int k0 = nb * 8 + tq * 2;
            float2 bb = *(const float2*)&bias[k0];
            uint32_t h, l;
            hsplit2(d[nb][0] + bb.x, d[nb][1] + bb.y, h, l);
            *(uint32_t*)&oh[nlo * CD + k0] = h;
            *(uint32_t*)&ol[nlo * CD + k0] = l;
            hsplit2(d[nb][2] + bb.x, d[nb][3] + bb.y, h, l);
            *(uint32_t*)&oh[nhi * CD + k0] = h;
            *(uint32_t*)&ol[nhi * CD + k0] = l;
        }
    }
}

// ---------------------------------------------------------------------------
// HMMA flash attention. BQ=128, BK=64. grid (32, 8), 256 threads.
// S = split-bf16 3-product; PV = fp16 P (single) x fp16 V (hi/lo) 2-product.
// ---------------------------------------------------------------------------
#define S_QH 0u
#define S_QL 32768u
#define S_KH 65536u
#define S_KL 98304u
#define S_VH 131072u
#define S_VL 163840u
#define S_STAGE 16384u
#define SMEM_FLASH 196608u

__global__ __launch_bounds__(256, 1) void flash_mma_kernel()
{
    extern __shared__ __align__(256) char sm[];
    const uint32_t su = s2u(sm);

    const int t = threadIdx.x;
    const int w = t >> 5;
    const int lane = t & 31;
    const int sub = lane >> 3;
    const int rowInM = lane & 7;
    const int b = blockIdx.y;
    const int q0 = blockIdx.x * 128;

    const __nv_bfloat16* Qhg = g_Qh + ((size_t)b * NTOK + q0) * CD;
    const __nv_bfloat16* Qlg = g_Ql + ((size_t)b * NTOK + q0) * CD;
    const __nv_bfloat16* Khg = g_Kh + (size_t)b * NTOK * CD;
    const __nv_bfloat16* Klg = g_Kl + (size_t)b * NTOK * CD;
    const __half* Vhg = g_Vh + (size_t)b * NTOK * CD;
    const __half* Vlg = g_Vl + (size_t)b * NTOK * CD;

    for (int i = t; i < 2048; i += 256) {
        int r = i >> 4, c = i & 15;
        uint32_t off = swz(r, c);
        cp16(su + S_QH + off, Qhg + (size_t)r * CD + c * 8);
        cp16(su + S_QL + off, Qlg + (size_t)r * CD + c * 8);
    }
    for (int i = t; i < 1024; i += 256) {
        int r = i >> 4, c = i & 15;
        uint32_t off = swz(r, c);
        cp16(su + S_KH + off, Khg + (size_t)r * CD + c * 8);
        cp16(su + S_KL + off, Klg + (size_t)r * CD + c * 8);
        cp16(su + S_VH + off, Vhg + (size_t)r * CD + c * 8);
        cp16(su + S_VL + off, Vlg + (size_t)r * CD + c * 8);
    }
    cp_commit();

    float o[16][4];
    #pragma unroll
    for (int f = 0; f < 16; f++)
        #pragma unroll
        for (int j = 0; j < 4; j++) o[f][j] = 0.f;
    float m0 = -1e30f, m1 = -1e30f, l0 = 0.f, l1 = 0.f;

    for (int kt = 0; kt < NKT; kt++) {
        const uint32_t st = (kt & 1) * S_STAGE;
        if (kt + 1 < NKT) {
            const uint32_t st2 = ((kt + 1) & 1) * S_STAGE;
            const size_t gofs = (size_t)(kt + 1) * 64 * CD;
            for (int i = t; i < 1024; i += 256) {
                int r = i >> 4, c = i & 15;
                uint32_t off = swz(r, c) + st2;
                size_t g = gofs + (size_t)r * CD + c * 8;
                cp16(su + S_KH + off, Khg + g);
                cp16(su + S_KL + off, Klg + g);
                cp16(su + S_VH + off, Vhg + g);
                cp16(su + S_VL + off, Vlg + g);
            }
            cp_commit();
            cp_wait1();
        } else {
            cp_wait0();
        }
        __syncthreads();

        // ---------- S = Q K^T (bf16, 3 products) ----------
        float s[8][4];
        #pragma unroll
        for (int f = 0; f < 8; f++)
            #pragma unroll
            for (int j = 0; j < 4; j++) s[f][j] = 0.f;

        #pragma unroll
        for (int kc = 0; kc < 8; kc++) {
            uint32_t qh[4], ql[4];
            {
                int row = w * 16 + rowInM + ((sub & 1) << 3);
                int c16 = kc * 2 + (sub >> 1);
                ldsm4(qh, su + S_QH + swz(row, c16));
                ldsm4(ql, su + S_QL + swz(row, c16));
            }
            #pragma unroll
            for (int nb = 0; nb < 4; nb++) {
                uint32_t kh4[4], kl4[4];
                int row = nb * 16 + rowInM + ((sub >> 1) << 3);
                int c16 = kc * 2 + (sub & 1);
                ldsm4(kh4, su + S_KH + st + swz(row, c16));
                ldsm4(kl4, su + S_KL + st + swz(row, c16));
                mma_bf(s[nb * 2],     qh, kh4[0], kh4[1]);
                mma_bf(s[nb * 2 + 1], qh, kh4[2], kh4[3]);
                mma_bf(s[nb * 2],     qh, kl4[0], kl4[1]);
                mma_bf(s[nb * 2 + 1], qh, kl4[2], kl4[3]);
                mma_bf(s[nb * 2],     ql, kh4[0], kh4[1]);
                mma_bf(s[nb * 2 + 1], ql, kh4[2], kh4[3]);
            }
        }

        // ---------- online softmax ----------
        float mx0 = -1e30f, mx1 = -1e30f;
        #pragma unroll
        for (int f = 0; f < 8; f++) {
            mx0 = fmaxf(mx0, fmaxf(s[f][0], s[f][1]));
            mx1 = fmaxf(mx1, fmaxf(s[f][2], s[f][3]));
        }
        mx0 = fmaxf(mx0, __shfl_xor_sync(0xffffffffu, mx0, 1));
        mx0 = fmaxf(mx0, __shfl_xor_sync(0xffffffffu, mx0, 2));
        mx1 = fmaxf(mx1, __shfl_xor_sync(0xffffffffu, mx1, 1));
        mx1 = fmaxf(mx1, __shfl_xor_sync(0xffffffffu, mx1, 2));
        float mn0 = fmaxf(m0, mx0), mn1 = fmaxf(m1, mx1);
        float c0f = fexp(m0 - mn0), c1f = fexp(m1 - mn1);
        m0 = mn0; m1 = mn1;

        uint32_t ph0[8], ph1[8];
        float ps0 = 0.f, ps1 = 0.f;
        #pragma unroll
        for (int f = 0; f < 8; f++) {
            float p00 = fexp(s[f][0] - m0);
            float p01 = fexp(s[f][1] - m0);
            float p10 = fexp(s[f][2] - m1);
            float p11 = fexp(s[f][3] - m1);
            ps0 += p00 + p01;
            ps1 += p10 + p11;
            ph0[f] = pack_h2(p00, p01);
            ph1[f] = pack_h2(p10, p11);
        }
        ps0 += __shfl_xor_sync(0xffffffffu, ps0, 1);
        ps0 += __shfl_xor_sync(0xffffffffu, ps0, 2);
        ps1 += __shfl_xor_sync(0xffffffffu, ps1, 1);
        ps1 += __shfl_xor_sync(0xffffffffu, ps1, 2);
        l0 = l0 * c0f + ps0;
        l1 = l1 * c1f + ps1;
        #pragma unroll
        for (int f = 0; f < 16; f++) {
            o[f][0] *= c0f; o[f][1] *= c0f;
            o[f][2] *= c1f; o[f][3] *= c1f;
        }

        // ---------- O += P V (fp16, 2 products) ----------
        #pragma unroll
        for (int kc = 0; kc < 4; kc++) {
            uint32_t a[4] = {ph0[kc * 2], ph1[kc * 2], ph0[kc * 2 + 1], ph1[kc * 2 + 1]};
            int row = kc * 16 + rowInM + ((sub & 1) << 3);
            #pragma unroll
            for (int vb = 0; vb < 8; vb++) {
                int c16 = vb * 2 + (sub >> 1);
                uint32_t vh4[4], vl4[4];
                ldsm4t(vh4, su + S_VH + st + swz(row, c16));
                ldsm4t(vl4, su + S_VL + st + swz(row, c16));
                mma_hf(o[vb * 2],     a, vh4[0], vh4[1]);
                mma_hf(o[vb * 2 + 1], a, vh4[2], vh4[3]);
                mma_hf(o[vb * 2],     a, vl4[0], vl4[1]);
                mma_hf(o[vb * 2 + 1], a, vl4[2], vl4[3]);
            }
        }
        __syncthreads();
    }

    // ---------- normalize + store Y (bf16 hi/lo) ----------
    const float i0 = 1.f / l0, i1 = 1.f / l1;
    const int g = lane >> 2, tq = lane & 3;
    const size_t r0 = (size_t)b * NTOK + q0 + w * 16 + g;
    const size_t r1 = r0 + 8;
    #pragma unroll
    for (int f = 0; f < 16; f++) {
        int col = f * 8 + tq * 2;
        uint32_t h, l;
        split2(o[f][0] * i0, o[f][1] * i0, h, l);
        *(uint32_t*)&g_Yh[r0 * CD + col] = h;
        *(uint32_t*)&g_Yl[r0 * CD + col] = l;
        split2(o[f][2] * i1, o[f][3] * i1, h, l);
        *(uint32_t*)&g_Yh[r1 * CD + col] = h;
        *(uint32_t*)&g_Yl[r1 * CD + col] = l;
    }
}

// ---------------------------------------------------------------------------
// HMMA output conv: out[b,c,n] = sum_v W[c][v] * Y[n][v] + wb[c]
// grid (32 n, 2 c, 8 b), 256 threads. All k=128 in smem, no staging.
// ---------------------------------------------------------------------------
#define OS_WH 0u
#define OS_WL 32768u
#define OS_YH 65536u
#define OS_YL 98304u
#define SMEM_OUT 131072u

__global__ __launch_bounds__(256, 1) void out_mma_kernel(
    const float* __restrict__ wb, float* __restrict__ out)
{
    extern __shared__ __align__(256) char sm[];
    const uint32_t su = s2u(sm);

    const int t = threadIdx.x;
    const int w = t >> 5;
    const int lane = t & 31;
    const int sub = lane >> 3;
    const int rowInM = lane & 7;
    const int b = blockIdx.z;
    const int c0t = blockIdx.y * 128;
    const int n0 = blockIdx.x * 128;

    for (int i = t; i < 2048; i += 256) {
        int r = i >> 4, ch = i & 15;
        uint32_t off = swz(r, ch);
        size_t gw = (size_t)(c0t + r) * CD + ch * 8;
        size_t gy = ((size_t)b * NTOK + n0 + r) * CD + ch * 8;
        cp16(su + OS_WH + off, g_Wwh + gw);
        cp16(su + OS_WL + off, g_Wwl + gw);
        cp16(su + OS_YH + off, g_Yh + gy);
        cp16(su + OS_YL + off, g_Yl + gy);
    }
    cp_commit();
    cp_wait0();
    __syncthreads();

    float d[16][4];
    #pragma unroll
    for (int i = 0; i < 16; i++)
        #pragma unroll
        for (int j = 0; j < 4; j++) d[i][j] = 0.f;

    #pragma unroll
    for (int kc = 0; kc < 8; kc++) {
        uint32_t ah[4], al[4];
        {
            int row = w * 16 + rowInM + ((sub & 1) << 3);
            int c16 = kc * 2 + (sub >> 1);
            ldsm4(ah, su + OS_WH + swz(row, c16));
            ldsm4(al, su + OS_WL + swz(row, c16));
        }
        #pragma unroll
        for (int nbp = 0; nbp < 8; nbp++) {
            uint32_t yh[4], yl[4];
            int row = nbp * 16 + rowInM + ((sub >> 1) << 3);
            int c16 = kc * 2 + (sub & 1);
            ldsm4(yh, su + OS_YH + swz(row, c16));
            ldsm4(yl, su + OS_YL + swz(row, c16));
            mma_bf(d[nbp * 2],     ah, yh[0], yh[1]);
            mma_bf(d[nbp * 2],     ah, yl[0], yl[1]);
            mma_bf(d[nbp * 2],     al, yh[0], yh[1]);
            mma_bf(d[nbp * 2 + 1], ah, yh[2], yh[3]);
            mma_bf(d[nbp * 2 + 1], ah, yl[2], yl[3]);
            mma_bf(d[nbp * 2 + 1], al, yh[2], yh[3]);
        }
    }

    const int g = lane >> 2, tq = lane & 3;
    const int clo = c0t + w * 16 + g;
    const int chi = clo + 8;
    const float wb0 = wb[clo], wb1 = wb[chi];
    float* ob = out + (size_t)b * CIN * NTOK;
    #pragma unroll
    for (int nb = 0; nb < 16; nb++) {
        int n = n0 + nb * 8 + tq * 2;
        *(float2*)&ob[(size_t)clo * NTOK + n] = make_float2(d[nb][0] + wb0, d[nb][1] + wb0);
        *(float2*)&ob[(size_t)chi * NTOK + n] = make_float2(d[nb][2] + wb1, d[nb][3] + wb1);
    }
}

// ---------------------------------------------------------------------------
extern "C" void kernel_launch(void* const* d_in, const int* in_sizes, int n_in,
                              void* d_out, int out_size)
{
    const float* x  = (const float*)d_in[0];
    const float* tw = (const float*)d_in[1];
    const float* tb = (const float*)d_in[2];
    const float* pw = (const float*)d_in[3];
    const float* pb = (const float*)d_in[4];
    const float* gw = (const float*)d_in[5];
    const float* gb = (const float*)d_in[6];
    const float* ww = (const float*)d_in[7];
    const float* wb = (const float*)d_in[8];
    float* out = (float*)d_out;
    (void)in_sizes; (void)n_in; (void)out_size;

    conv_x_kernel<<<(BATCH * CIN * NTOK) / 1024, 256>>>(x);
    conv_w_kernel<<<dim3((CD * CIN) / 1024, 4), 256>>>(tw, pw, gw, ww);

    cudaFuncSetAttribute(proj_mma_kernel,
                         cudaFuncAttributeMaxDynamicSharedMemorySize, SMEM_PROJ);
    proj_mma_kernel<<<dim3(NTOK / 128, BATCH, 3), 256, SMEM_PROJ>>>(tb, pb, gb);

    cudaFuncSetAttribute(flash_mma_kernel,
                         cudaFuncAttributeMaxDynamicSharedMemorySize, SMEM_FLASH);
    flash_mma_kernel<<<dim3(NTOK / 128, BATCH), 256, SMEM_FLASH>>>();

    cudaFuncSetAttribute(out_mma_kernel,
                         cudaFuncAttributeMaxDynamicSharedMemorySize, SMEM_OUT);
    out_mma_kernel<<<dim3(NTOK / 128, CIN / 128, BATCH), 256, SMEM_OUT>>>(wb, out);
}

// round 8
// speedup vs baseline: 4.8403x; 1.1322x over previous
#include <cuda_runtime.h>
#include <cuda_bf16.h>
#include <cuda_fp16.h>
#include <cstdint>
#include <math.h>

#define BATCH 8
#define CIN   256
#define NTOK  4096
#define CD    128
#define NKT   64

// ---------------- device scratch ----------------
__device__ __nv_bfloat16 g_Xh[BATCH * CIN * NTOK];
__device__ __nv_bfloat16 g_Xl[BATCH * CIN * NTOK];
__device__ __nv_bfloat16 g_Twh[CD * CIN], g_Twl[CD * CIN];
__device__ __nv_bfloat16 g_Pwh[CD * CIN], g_Pwl[CD * CIN];
__device__ __nv_bfloat16 g_Gwh[CD * CIN], g_Gwl[CD * CIN];
__device__ __nv_bfloat16 g_Wwh[CIN * CD], g_Wwl[CIN * CD];
__device__ __nv_bfloat16 g_Qh[BATCH * NTOK * CD], g_Ql[BATCH * NTOK * CD];
__device__ __nv_bfloat16 g_Kh[BATCH * NTOK * CD], g_Kl[BATCH * NTOK * CD];
__device__ __half        g_Vh[BATCH * NTOK * CD];
__device__ __nv_bfloat16 g_Yh[BATCH * NTOK * CD], g_Yl[BATCH * NTOK * CD];

// ---------------- helpers ----------------
__device__ __forceinline__ uint32_t s2u(const void* p) {
    uint32_t a;
    asm("{ .reg .u64 t; cvta.to.shared.u64 t, %1; cvt.u32.u64 %0, t; }"
        : "=r"(a) : "l"(p));
    return a;
}
__device__ __forceinline__ void ldsm4(uint32_t* r, uint32_t a) {
    asm volatile("ldmatrix.sync.aligned.m8n8.x4.shared.b16 {%0,%1,%2,%3}, [%4];"
        : "=r"(r[0]), "=r"(r[1]), "=r"(r[2]), "=r"(r[3]) : "r"(a));
}
__device__ __forceinline__ void ldsm4t(uint32_t* r, uint32_t a) {
    asm volatile("ldmatrix.sync.aligned.m8n8.x4.trans.shared.b16 {%0,%1,%2,%3}, [%4];"
        : "=r"(r[0]), "=r"(r[1]), "=r"(r[2]), "=r"(r[3]) : "r"(a));
}
__device__ __forceinline__ void mma_bf(float* d, const uint32_t* a, uint32_t b0, uint32_t b1) {
    asm volatile(
        "mma.sync.aligned.m16n8k16.row.col.f32.bf16.bf16.f32 "
        "{%0,%1,%2,%3},{%4,%5,%6,%7},{%8,%9},{%0,%1,%2,%3};"
        : "+f"(d[0]), "+f"(d[1]), "+f"(d[2]), "+f"(d[3])
        : "r"(a[0]), "r"(a[1]), "r"(a[2]), "r"(a[3]), "r"(b0), "r"(b1));
}
__device__ __forceinline__ void mma_hf(float* d, const uint32_t* a, uint32_t b0, uint32_t b1) {
    asm volatile(
        "mma.sync.aligned.m16n8k16.row.col.f32.f16.f16.f32 "
        "{%0,%1,%2,%3},{%4,%5,%6,%7},{%8,%9},{%0,%1,%2,%3};"
        : "+f"(d[0]), "+f"(d[1]), "+f"(d[2]), "+f"(d[3])
        : "r"(a[0]), "r"(a[1]), "r"(a[2]), "r"(a[3]), "r"(b0), "r"(b1));
}
__device__ __forceinline__ void cp16(uint32_t dst, const void* src) {
    asm volatile("cp.async.cg.shared.global [%0], [%1], 16;" :: "r"(dst), "l"(src));
}
__device__ __forceinline__ void cp_commit() { asm volatile("cp.async.commit_group;"); }
__device__ __forceinline__ void cp_wait1() { asm volatile("cp.async.wait_group 1;" ::: "memory"); }
__device__ __forceinline__ void cp_wait0() { asm volatile("cp.async.wait_group 0;" ::: "memory"); }

__device__ __forceinline__ uint32_t swz(int r, int c16) {
    return (uint32_t)(r * 256 + ((c16 ^ (r & 7)) << 4));
}
__device__ __forceinline__ uint32_t swzB(int r, int c16) {
    return (uint32_t)(r * 128 + ((c16 ^ (r & 7)) << 4));
}

// exp on the FMA pipe
__device__ __forceinline__ float fexp(float x) {
    float z = fmaxf(x * 1.4426950408889634f, -126.f);
    float r = z + 12582912.f;
    int ni = __float_as_int(r) - 0x4B400000;
    float f = z - (r - 12582912.f);
    float u = f * 0.6931471805599453f;
    float e = 1.9841269841e-4f;
    e = fmaf(e, u, 1.3888888889e-3f);
    e = fmaf(e, u, 8.3333333333e-3f);
    e = fmaf(e, u, 4.1666666667e-2f);
    e = fmaf(e, u, 1.6666666667e-1f);
    e = fmaf(e, u, 0.5f);
    e = fmaf(e, u, 1.0f);
    e = fmaf(e, u, 1.0f);
    return e * __int_as_float((ni + 127) << 23);
}

__device__ __forceinline__ void bfsplit(float v, unsigned short& h, unsigned short& l) {
    __nv_bfloat16 bh = __float2bfloat16_rn(v);
    __nv_bfloat16 bl = __float2bfloat16_rn(v - __bfloat162float(bh));
    h = __bfloat16_as_ushort(bh);
    l = __bfloat16_as_ushort(bl);
}
__device__ __forceinline__ void split2(float x, float y, uint32_t& h, uint32_t& l) {
    unsigned short hx, lx, hy, ly;
    bfsplit(x, hx, lx);
    bfsplit(y, hy, ly);
    h = (uint32_t)hx | ((uint32_t)hy << 16);
    l = (uint32_t)lx | ((uint32_t)ly << 16);
}
// pack (lo_elem, hi_elem) -> f16x2
__device__ __forceinline__ uint32_t pack_h2(float lo, float hi) {
    uint32_t r;
    asm("cvt.rn.f16x2.f32 %0, %1, %2;" : "=r"(r) : "f"(hi), "f"(lo));
    return r;
}

// ---------------------------------------------------------------------------
// conversion passes
// ---------------------------------------------------------------------------
__global__ __launch_bounds__(256) void conv_x_kernel(const float* __restrict__ x)
{
    size_t i = ((size_t)blockIdx.x * 256 + threadIdx.x) * 4;
    float4 v = *(const float4*)&x[i];
    unsigned short h[4], l[4];
    bfsplit(v.x, h[0], l[0]); bfsplit(v.y, h[1], l[1]);
    bfsplit(v.z, h[2], l[2]); bfsplit(v.w, h[3], l[3]);
    *(uint2*)&g_Xh[i] = make_uint2((unsigned)h[0] | ((unsigned)h[1] << 16),
                                   (unsigned)h[2] | ((unsigned)h[3] << 16));
    *(uint2*)&g_Xl[i] = make_uint2((unsigned)l[0] | ((unsigned)l[1] << 16),
                                   (unsigned)l[2] | ((unsigned)l[3] << 16));
}

__global__ __launch_bounds__(256) void conv_w_kernel(
    const float* __restrict__ tw, const float* __restrict__ pw,
    const float* __restrict__ gw, const float* __restrict__ ww)
{
    const float* src; __nv_bfloat16* dh; __nv_bfloat16* dl;
    switch (blockIdx.y) {
        case 0: src = tw; dh = g_Twh; dl = g_Twl; break;
        case 1: src = pw; dh = g_Pwh; dl = g_Pwl; break;
        case 2: src = gw; dh = g_Gwh; dl = g_Gwl; break;
        default: src = ww; dh = g_Wwh; dl = g_Wwl; break;
    }
    size_t i = ((size_t)blockIdx.x * 256 + threadIdx.x) * 4;
    float4 v = *(const float4*)&src[i];
    unsigned short h[4], l[4];
    bfsplit(v.x, h[0], l[0]); bfsplit(v.y, h[1], l[1]);
    bfsplit(v.z, h[2], l[2]); bfsplit(v.w, h[3], l[3]);
    *(uint2*)&dh[i] = make_uint2((unsigned)h[0] | ((unsigned)h[1] << 16),
                                 (unsigned)h[2] | ((unsigned)h[3] << 16));
    *(uint2*)&dl[i] = make_uint2((unsigned)l[0] | ((unsigned)l[1] << 16),
                                 (unsigned)l[2] | ((unsigned)l[3] << 16));
}

// ---------------------------------------------------------------------------
// HMMA projections. grid (32,8,3), 256 threads.
// ---------------------------------------------------------------------------
#define PS_XH(s) ((s) * 65536u)
#define PS_XL(s) ((s) * 65536u + 16384u)
#define PS_WH(s) ((s) * 65536u + 32768u)
#define PS_WL(s) ((s) * 65536u + 49152u)
#define SMEM_PROJ 131072u

__global__ __launch_bounds__(256, 1) void proj_mma_kernel(
    const float* __restrict__ tb, const float* __restrict__ pb,
    const float* __restrict__ gb)
{
    extern __shared__ __align__(256) char sm[];
    const uint32_t su = s2u(sm);

    const int t = threadIdx.x;
    const int w = t >> 5;
    const int lane = t & 31;
    const int sub = lane >> 3;
    const int rowInM = lane & 7;
    const int b = blockIdx.y;
    const int which = blockIdx.z;
    const int n0 = blockIdx.x * 128;

    const __nv_bfloat16 *wh, *wl; const float* bias;
    if (which == 0)      { wh = g_Twh; wl = g_Twl; bias = tb; }
    else if (which == 1) { wh = g_Pwh; wl = g_Pwl; bias = pb; }
    else                 { wh = g_Gwh; wl = g_Gwl; bias = gb; }
    const __nv_bfloat16* xh = g_Xh + (size_t)b * CIN * NTOK;
    const __nv_bfloat16* xl = g_Xl + (size_t)b * CIN * NTOK;

    auto load_stage = [&](int c0, int s) {
        for (int i = t; i < 1024; i += 256) {
            int r = i >> 4, ch = i & 15;
            uint32_t off = swz(r, ch);
            size_t g = (size_t)(c0 + r) * NTOK + n0 + ch * 8;
            cp16(su + PS_XH(s) + off, xh + g);
            cp16(su + PS_XL(s) + off, xl + g);
        }
        for (int i = t; i < 1024; i += 256) {
            int r = i >> 3, ch = i & 7;
            uint32_t off = swzB(r, ch);
            size_t g = (size_t)r * CIN + c0 + ch * 8;
            cp16(su + PS_WH(s) + off, wh + g);
            cp16(su + PS_WL(s) + off, wl + g);
        }
    };

    float d[16][4];
    #pragma unroll
    for (int i = 0; i < 16; i++)
        #pragma unroll
        for (int j = 0; j < 4; j++) d[i][j] = 0.f;

    load_stage(0, 0);
    cp_commit();

    for (int ck = 0; ck < 4; ck++) {
        if (ck < 3) { load_stage((ck + 1) * 64, (ck + 1) & 1); cp_commit(); cp_wait1(); }
        else cp_wait0();
        __syncthreads();
        const int s = ck & 1;
        #pragma unroll
        for (int kc = 0; kc < 4; kc++) {
            uint32_t ah[4], al[4];
            {
                int row = kc * 16 + rowInM + ((sub >> 1) << 3);
                int c16 = w * 2 + (sub & 1);
                ldsm4t(ah, su + PS_XH(s) + swz(row, c16));
                ldsm4t(al, su + PS_XL(s) + swz(row, c16));
            }
            #pragma unroll
            for (int nbp = 0; nbp < 8; nbp++) {
                uint32_t bh[4], bl[4];
                int row = nbp * 16 + rowInM + ((sub >> 1) << 3);
                int c16 = kc * 2 + (sub & 1);
                ldsm4(bh, su + PS_WH(s) + swzB(row, c16));
                ldsm4(bl, su + PS_WL(s) + swzB(row, c16));
                mma_bf(d[nbp * 2],     ah, bh[0], bh[1]);
                mma_bf(d[nbp * 2],     ah, bl[0], bl[1]);
                mma_bf(d[nbp * 2],     al, bh[0], bh[1]);
                mma_bf(d[nbp * 2 + 1], ah, bh[2], bh[3]);
                mma_bf(d[nbp * 2 + 1], ah, bl[2], bl[3]);
                mma_bf(d[nbp * 2 + 1], al, bh[2], bh[3]);
            }
        }
        __syncthreads();
    }

    const int g = lane >> 2, tq = lane & 3;
    const size_t nlo = (size_t)(n0 + w * 16 + g);
    const size_t nhi = nlo + 8;
    if (which < 2) {
        __nv_bfloat16* oh = (which == 0 ? g_Qh : g_Kh) + (size_t)b * NTOK * CD;
        __nv_bfloat16* ol = (which == 0 ? g_Ql : g_Kl) + (size_t)b * NTOK * CD;
        #pragma unroll
        for (int nb = 0; nb < 16; nb++) {
            int k0 = nb * 8 + tq * 2;
            float2 bb = *(const float2*)&bias[k0];
            uint32_t h, l;
            split2(d[nb][0] + bb.x, d[nb][1] + bb.y, h, l);
            *(uint32_t*)&oh[nlo * CD + k0] = h;
            *(uint32_t*)&ol[nlo * CD + k0] = l;
            split2(d[nb][2] + bb.x, d[nb][3] + bb.y, h, l);
            *(uint32_t*)&oh[nhi * CD + k0] = h;
            *(uint32_t*)&ol[nhi * CD + k0] = l;
        }
    } else {
        __half* oh = g_Vh + (size_t)b * NTOK * CD;
        #pragma unroll
        for (int nb = 0; nb < 16; nb++) {
            int k0 = nb * 8 + tq * 2;
            float2 bb = *(const float2*)&bias[k0];
            *(uint32_t*)&oh[nlo * CD + k0] = pack_h2(d[nb][0] + bb.x, d[nb][1] + bb.y);
            *(uint32_t*)&oh[nhi * CD + k0] = pack_h2(d[nb][2] + bb.x, d[nb][3] + bb.y);
        }
    }
}

// ---------------------------------------------------------------------------
// HMMA flash attention. BQ=128, BK=64. grid (32, 8), 256 threads.
// S = split-bf16 3-product; PV = fp16 P x fp16 V single product.
// ---------------------------------------------------------------------------
#define S_QH 0u
#define S_QL 32768u
#define S_KH 65536u
#define S_KL 98304u
#define S_VH 131072u
#define S_STAGE 16384u
#define SMEM_FLASH 163840u

__global__ __launch_bounds__(256, 1) void flash_mma_kernel()
{
    extern __shared__ __align__(256) char sm[];
    const uint32_t su = s2u(sm);

    const int t = threadIdx.x;
    const int w = t >> 5;
    const int lane = t & 31;
    const int sub = lane >> 3;
    const int rowInM = lane & 7;
    const int b = blockIdx.y;
    const int q0 = blockIdx.x * 128;

    const __nv_bfloat16* Qhg = g_Qh + ((size_t)b * NTOK + q0) * CD;
    const __nv_bfloat16* Qlg = g_Ql + ((size_t)b * NTOK + q0) * CD;
    const __nv_bfloat16* Khg = g_Kh + (size_t)b * NTOK * CD;
    const __nv_bfloat16* Klg = g_Kl + (size_t)b * NTOK * CD;
    const __half* Vhg = g_Vh + (size_t)b * NTOK * CD;

    for (int i = t; i < 2048; i += 256) {
        int r = i >> 4, c = i & 15;
        uint32_t off = swz(r, c);
        cp16(su + S_QH + off, Qhg + (size_t)r * CD + c * 8);
        cp16(su + S_QL + off, Qlg + (size_t)r * CD + c * 8);
    }
    for (int i = t; i < 1024; i += 256) {
        int r = i >> 4, c = i & 15;
        uint32_t off = swz(r, c);
        cp16(su + S_KH + off, Khg + (size_t)r * CD + c * 8);
        cp16(su + S_KL + off, Klg + (size_t)r * CD + c * 8);
        cp16(su + S_VH + off, Vhg + (size_t)r * CD + c * 8);
    }
    cp_commit();

    float o[16][4];
    #pragma unroll
    for (int f = 0; f < 16; f++)
        #pragma unroll
        for (int j = 0; j < 4; j++) o[f][j] = 0.f;
    float m0 = -1e30f, m1 = -1e30f, l0 = 0.f, l1 = 0.f;

    for (int kt = 0; kt < NKT; kt++) {
        const uint32_t st = (kt & 1) * S_STAGE;
        if (kt + 1 < NKT) {
            const uint32_t st2 = ((kt + 1) & 1) * S_STAGE;
            const size_t gofs = (size_t)(kt + 1) * 64 * CD;
            for (int i = t; i < 1024; i += 256) {
                int r = i >> 4, c = i & 15;
                uint32_t off = swz(r, c) + st2;
                size_t g = gofs + (size_t)r * CD + c * 8;
                cp16(su + S_KH + off, Khg + g);
                cp16(su + S_KL + off, Klg + g);
                cp16(su + S_VH + off, Vhg + g);
            }
            cp_commit();
            cp_wait1();
        } else {
            cp_wait0();
        }
        __syncthreads();

        // ---------- S = Q K^T (bf16, 3 products) ----------
        float s[8][4];
        #pragma unroll
        for (int f = 0; f < 8; f++)
            #pragma unroll
            for (int j = 0; j < 4; j++) s[f][j] = 0.f;

        #pragma unroll
        for (int kc = 0; kc < 8; kc++) {
            uint32_t qh[4], ql[4];
            {
                int row = w * 16 + rowInM + ((sub & 1) << 3);
                int c16 = kc * 2 + (sub >> 1);
                ldsm4(qh, su + S_QH + swz(row, c16));
                ldsm4(ql, su + S_QL + swz(row, c16));
            }
            #pragma unroll
            for (int nb = 0; nb < 4; nb++) {
                uint32_t kh4[4], kl4[4];
                int row = nb * 16 + rowInM + ((sub >> 1) << 3);
                int c16 = kc * 2 + (sub & 1);
                ldsm4(kh4, su + S_KH + st + swz(row, c16));
                ldsm4(kl4, su + S_KL + st + swz(row, c16));
                mma_bf(s[nb * 2],     qh, kh4[0], kh4[1]);
                mma_bf(s[nb * 2 + 1], qh, kh4[2], kh4[3]);
                mma_bf(s[nb * 2],     qh, kl4[0], kl4[1]);
                mma_bf(s[nb * 2 + 1], qh, kl4[2], kl4[3]);
                mma_bf(s[nb * 2],     ql, kh4[0], kh4[1]);
                mma_bf(s[nb * 2 + 1], ql, kh4[2], kh4[3]);
            }
        }

        // ---------- online softmax (rescale skipped when max stable) ----------
        float mx0 = -1e30f, mx1 = -1e30f;
        #pragma unroll
        for (int f = 0; f < 8; f++) {
            mx0 = fmaxf(mx0, fmaxf(s[f][0], s[f][1]));
            mx1 = fmaxf(mx1, fmaxf(s[f][2], s[f][3]));
        }
        mx0 = fmaxf(mx0, __shfl_xor_sync(0xffffffffu, mx0, 1));
        mx0 = fmaxf(mx0, __shfl_xor_sync(0xffffffffu, mx0, 2));
        mx1 = fmaxf(mx1, __shfl_xor_sync(0xffffffffu, mx1, 1));
        mx1 = fmaxf(mx1, __shfl_xor_sync(0xffffffffu, mx1, 2));

        uint32_t upd = __ballot_sync(0xffffffffu, (mx0 > m0) || (mx1 > m1));
        if (upd) {
            float mn0 = fmaxf(m0, mx0), mn1 = fmaxf(m1, mx1);
            float c0f = fexp(m0 - mn0), c1f = fexp(m1 - mn1);
            m0 = mn0; m1 = mn1;
            l0 *= c0f; l1 *= c1f;
            #pragma unroll
            for (int f = 0; f < 16; f++) {
                o[f][0] *= c0f; o[f][1] *= c0f;
                o[f][2] *= c1f; o[f][3] *= c1f;
            }
        }

        uint32_t ph0[8], ph1[8];
        float ps0 = 0.f, ps1 = 0.f;
        #pragma unroll
        for (int f = 0; f < 8; f++) {
            float p00 = fexp(s[f][0] - m0);
            float p01 = fexp(s[f][1] - m0);
            float p10 = fexp(s[f][2] - m1);
            float p11 = fexp(s[f][3] - m1);
            ps0 += p00 + p01;
            ps1 += p10 + p11;
            ph0[f] = pack_h2(p00, p01);
            ph1[f] = pack_h2(p10, p11);
        }
        ps0 += __shfl_xor_sync(0xffffffffu, ps0, 1);
        ps0 += __shfl_xor_sync(0xffffffffu, ps0, 2);
        ps1 += __shfl_xor_sync(0xffffffffu, ps1, 1);
        ps1 += __shfl_xor_sync(0xffffffffu, ps1, 2);
        l0 += ps0;
        l1 += ps1;

        // ---------- O += P V (fp16, single product) ----------
        #pragma unroll
        for (int kc = 0; kc < 4; kc++) {
            uint32_t a[4] = {ph0[kc * 2], ph1[kc * 2], ph0[kc * 2 + 1], ph1[kc * 2 + 1]};
            int row = kc * 16 + rowInM + ((sub & 1) << 3);
            #pragma unroll
            for (int vb = 0; vb < 8; vb++) {
                int c16 = vb * 2 + (sub >> 1);
                uint32_t vh4[4];
                ldsm4t(vh4, su + S_VH + st + swz(row, c16));
                mma_hf(o[vb * 2],     a, vh4[0], vh4[1]);
                mma_hf(o[vb * 2 + 1], a, vh4[2], vh4[3]);
            }
        }
        __syncthreads();
    }

    // ---------- normalize + store Y (bf16 hi/lo) ----------
    const float i0 = 1.f / l0, i1 = 1.f / l1;
    const int g = lane >> 2, tq = lane & 3;
    const size_t r0 = (size_t)b * NTOK + q0 + w * 16 + g;
    const size_t r1 = r0 + 8;
    #pragma unroll
    for (int f = 0; f < 16; f++) {
        int col = f * 8 + tq * 2;
        uint32_t h, l;
        split2(o[f][0] * i0, o[f][1] * i0, h, l);
        *(uint32_t*)&g_Yh[r0 * CD + col] = h;
        *(uint32_t*)&g_Yl[r0 * CD + col] = l;
        split2(o[f][2] * i1, o[f][3] * i1, h, l);
        *(uint32_t*)&g_Yh[r1 * CD + col] = h;
        *(uint32_t*)&g_Yl[r1 * CD + col] = l;
    }
}

// ---------------------------------------------------------------------------
// HMMA output conv. grid (32 n, 2 c, 8 b), 256 threads.
// ---------------------------------------------------------------------------
#define OS_WH 0u
#define OS_WL 32768u
#define OS_YH 65536u
#define OS_YL 98304u
#define SMEM_OUT 131072u

__global__ __launch_bounds__(256, 1) void out_mma_kernel(
    const float* __restrict__ wb, float* __restrict__ out)
{
    extern __shared__ __align__(256) char sm[];
    const uint32_t su = s2u(sm);

    const int t = threadIdx.x;
    const int w = t >> 5;
    const int lane = t & 31;
    const int sub = lane >> 3;
    const int rowInM = lane & 7;
    const int b = blockIdx.z;
    const int c0t = blockIdx.y * 128;
    const int n0 = blockIdx.x * 128;

    for (int i = t; i < 2048; i += 256) {
        int r = i >> 4, ch = i & 15;
        uint32_t off = swz(r, ch);
        size_t gw = (size_t)(c0t + r) * CD + ch * 8;
        size_t gy = ((size_t)b * NTOK + n0 + r) * CD + ch * 8;
        cp16(su + OS_WH + off, g_Wwh + gw);
        cp16(su + OS_WL + off, g_Wwl + gw);
        cp16(su + OS_YH + off, g_Yh + gy);
        cp16(su + OS_YL + off, g_Yl + gy);
    }
    cp_commit();
    cp_wait0();
    __syncthreads();

    float d[16][4];
    #pragma unroll
    for (int i = 0; i < 16; i++)
        #pragma unroll
        for (int j = 0; j < 4; j++) d[i][j] = 0.f;

    #pragma unroll
    for (int kc = 0; kc < 8; kc++) {
        uint32_t ah[4], al[4];
        {
            int row = w * 16 + rowInM + ((sub & 1) << 3);
            int c16 = kc * 2 + (sub >> 1);
            ldsm4(ah, su + OS_WH + swz(row, c16));
            ldsm4(al, su + OS_WL + swz(row, c16));
        }
        #pragma unroll
        for (int nbp = 0; nbp < 8; nbp++) {
            uint32_t yh[4], yl[4];
            int row = nbp * 16 + rowInM + ((sub >> 1) << 3);
            int c16 = kc * 2 + (sub & 1);
            ldsm4(yh, su + OS_YH + swz(row, c16));
            ldsm4(yl, su + OS_YL + swz(row, c16));
            mma_bf(d[nbp * 2],     ah, yh[0], yh[1]);
            mma_bf(d[nbp * 2],     ah, yl[0], yl[1]);
            mma_bf(d[nbp * 2],     al, yh[0], yh[1]);
            mma_bf(d[nbp * 2 + 1], ah, yh[2], yh[3]);
            mma_bf(d[nbp * 2 + 1], ah, yl[2], yl[3]);
            mma_bf(d[nbp * 2 + 1], al, yh[2], yh[3]);
        }
    }

    const int g = lane >> 2, tq = lane & 3;
    const int clo = c0t + w * 16 + g;
    const int chi = clo + 8;
    const float wb0 = wb[clo], wb1 = wb[chi];
    float* ob = out + (size_t)b * CIN * NTOK;
    #pragma unroll
    for (int nb = 0; nb < 16; nb++) {
        int n = n0 + nb * 8 + tq * 2;
        *(float2*)&ob[(size_t)clo * NTOK + n] = make_float2(d[nb][0] + wb0, d[nb][1] + wb0);
        *(float2*)&ob[(size_t)chi * NTOK + n] = make_float2(d[nb][2] + wb1, d[nb][3] + wb1);
    }
}

// ---------------------------------------------------------------------------
extern "C" void kernel_launch(void* const* d_in, const int* in_sizes, int n_in,
                              void* d_out, int out_size)
{
    const float* x  = (const float*)d_in[0];
    const float* tw = (const float*)d_in[1];
    const float* tb = (const float*)d_in[2];
    const float* pw = (const float*)d_in[3];
    const float* pb = (const float*)d_in[4];
    const float* gw = (const float*)d_in[5];
    const float* gb = (const float*)d_in[6];
    const float* ww = (const float*)d_in[7];
    const float* wb = (const float*)d_in[8];
    float* out = (float*)d_out;
    (void)in_sizes; (void)n_in; (void)out_size;

    conv_x_kernel<<<(BATCH * CIN * NTOK) / 1024, 256>>>(x);
    conv_w_kernel<<<dim3((CD * CIN) / 1024, 4), 256>>>(tw, pw, gw, ww);

    cudaFuncSetAttribute(proj_mma_kernel,
                         cudaFuncAttributeMaxDynamicSharedMemorySize, SMEM_PROJ);
    proj_mma_kernel<<<dim3(NTOK / 128, BATCH, 3), 256, SMEM_PROJ>>>(tb, pb, gb);

    cudaFuncSetAttribute(flash_mma_kernel,
                         cudaFuncAttributeMaxDynamicSharedMemorySize, SMEM_FLASH);
    flash_mma_kernel<<<dim3(NTOK / 128, BATCH), 256, SMEM_FLASH>>>();

    cudaFuncSetAttribute(out_mma_kernel,
                         cudaFuncAttributeMaxDynamicSharedMemorySize, SMEM_OUT);
    out_mma_kernel<<<dim3(NTOK / 128, CIN / 128, BATCH), 256, SMEM_OUT>>>(wb, out);
}

// round 9
// speedup vs baseline: 4.8520x; 1.0024x over previous
#include <cuda_runtime.h>
#include <cuda_bf16.h>
#include <cuda_fp16.h>
#include <cstdint>
#include <math.h>

#define BATCH 8
#define CIN   256
#define NTOK  4096
#define CD    128
#define NKT   64

// ---------------- device scratch ----------------
__device__ __nv_bfloat16 g_Xh[BATCH * CIN * NTOK];
__device__ __nv_bfloat16 g_Xl[BATCH * CIN * NTOK];
__device__ __nv_bfloat16 g_Twh[CD * CIN], g_Twl[CD * CIN];
__device__ __nv_bfloat16 g_Pwh[CD * CIN], g_Pwl[CD * CIN];
__device__ __nv_bfloat16 g_Gwh[CD * CIN], g_Gwl[CD * CIN];
__device__ __nv_bfloat16 g_Wwh[CIN * CD], g_Wwl[CIN * CD];
__device__ __nv_bfloat16 g_Qh[BATCH * NTOK * CD], g_Ql[BATCH * NTOK * CD];
__device__ __nv_bfloat16 g_Kh[BATCH * NTOK * CD], g_Kl[BATCH * NTOK * CD];
__device__ __half        g_Vh[BATCH * NTOK * CD];
__device__ __nv_bfloat16 g_Yh[BATCH * NTOK * CD], g_Yl[BATCH * NTOK * CD];

// ---------------- helpers ----------------
__device__ __forceinline__ uint32_t s2u(const void* p) {
    uint32_t a;
    asm("{ .reg .u64 t; cvta.to.shared.u64 t, %1; cvt.u32.u64 %0, t; }"
        : "=r"(a) : "l"(p));
    return a;
}
__device__ __forceinline__ void ldsm4(uint32_t* r, uint32_t a) {
    asm volatile("ldmatrix.sync.aligned.m8n8.x4.shared.b16 {%0,%1,%2,%3}, [%4];"
        : "=r"(r[0]), "=r"(r[1]), "=r"(r[2]), "=r"(r[3]) : "r"(a));
}
__device__ __forceinline__ void ldsm4t(uint32_t* r, uint32_t a) {
    asm volatile("ldmatrix.sync.aligned.m8n8.x4.trans.shared.b16 {%0,%1,%2,%3}, [%4];"
        : "=r"(r[0]), "=r"(r[1]), "=r"(r[2]), "=r"(r[3]) : "r"(a));
}
__device__ __forceinline__ void mma_bf(float* d, const uint32_t* a, uint32_t b0, uint32_t b1) {
    asm volatile(
        "mma.sync.aligned.m16n8k16.row.col.f32.bf16.bf16.f32 "
        "{%0,%1,%2,%3},{%4,%5,%6,%7},{%8,%9},{%0,%1,%2,%3};"
        : "+f"(d[0]), "+f"(d[1]), "+f"(d[2]), "+f"(d[3])
        : "r"(a[0]), "r"(a[1]), "r"(a[2]), "r"(a[3]), "r"(b0), "r"(b1));
}
__device__ __forceinline__ void mma_hf(float* d, const uint32_t* a, uint32_t b0, uint32_t b1) {
    asm volatile(
        "mma.sync.aligned.m16n8k16.row.col.f32.f16.f16.f32 "
        "{%0,%1,%2,%3},{%4,%5,%6,%7},{%8,%9},{%0,%1,%2,%3};"
        : "+f"(d[0]), "+f"(d[1]), "+f"(d[2]), "+f"(d[3])
        : "r"(a[0]), "r"(a[1]), "r"(a[2]), "r"(a[3]), "r"(b0), "r"(b1));
}
__device__ __forceinline__ void cp16(uint32_t dst, const void* src) {
    asm volatile("cp.async.cg.shared.global [%0], [%1], 16;" :: "r"(dst), "l"(src));
}
__device__ __forceinline__ void cp_commit() { asm volatile("cp.async.commit_group;"); }
__device__ __forceinline__ void cp_wait1() { asm volatile("cp.async.wait_group 1;" ::: "memory"); }
__device__ __forceinline__ void cp_wait0() { asm volatile("cp.async.wait_group 0;" ::: "memory"); }

__device__ __forceinline__ uint32_t swz(int r, int c16) {
    return (uint32_t)(r * 256 + ((c16 ^ (r & 7)) << 4));
}
__device__ __forceinline__ uint32_t swzB(int r, int c16) {
    return (uint32_t)(r * 128 + ((c16 ^ (r & 7)) << 4));
}

// exp on the FMA pipe
__device__ __forceinline__ float fexp(float x) {
    float z = fmaxf(x * 1.4426950408889634f, -126.f);
    float r = z + 12582912.f;
    int ni = __float_as_int(r) - 0x4B400000;
    float f = z - (r - 12582912.f);
    float u = f * 0.6931471805599453f;
    float e = 1.9841269841e-4f;
    e = fmaf(e, u, 1.3888888889e-3f);
    e = fmaf(e, u, 8.3333333333e-3f);
    e = fmaf(e, u, 4.1666666667e-2f);
    e = fmaf(e, u, 1.6666666667e-1f);
    e = fmaf(e, u, 0.5f);
    e = fmaf(e, u, 1.0f);
    e = fmaf(e, u, 1.0f);
    return e * __int_as_float((ni + 127) << 23);
}

__device__ __forceinline__ void bfsplit(float v, unsigned short& h, unsigned short& l) {
    __nv_bfloat16 bh = __float2bfloat16_rn(v);
    __nv_bfloat16 bl = __float2bfloat16_rn(v - __bfloat162float(bh));
    h = __bfloat16_as_ushort(bh);
    l = __bfloat16_as_ushort(bl);
}
__device__ __forceinline__ void split2(float x, float y, uint32_t& h, uint32_t& l) {
    unsigned short hx, lx, hy, ly;
    bfsplit(x, hx, lx);
    bfsplit(y, hy, ly);
    h = (uint32_t)hx | ((uint32_t)hy << 16);
    l = (uint32_t)lx | ((uint32_t)ly << 16);
}
// pack (lo_elem, hi_elem) -> f16x2
__device__ __forceinline__ uint32_t pack_h2(float lo, float hi) {
    uint32_t r;
    asm("cvt.rn.f16x2.f32 %0, %1, %2;" : "=r"(r) : "f"(hi), "f"(lo));
    return r;
}

// ---------------------------------------------------------------------------
// conversion passes
// ---------------------------------------------------------------------------
__global__ __launch_bounds__(256) void conv_x_kernel(const float* __restrict__ x)
{
    size_t i = ((size_t)blockIdx.x * 256 + threadIdx.x) * 4;
    float4 v = *(const float4*)&x[i];
    unsigned short h[4], l[4];
    bfsplit(v.x, h[0], l[0]); bfsplit(v.y, h[1], l[1]);
    bfsplit(v.z, h[2], l[2]); bfsplit(v.w, h[3], l[3]);
    *(uint2*)&g_Xh[i] = make_uint2((unsigned)h[0] | ((unsigned)h[1] << 16),
                                   (unsigned)h[2] | ((unsigned)h[3] << 16));
    *(uint2*)&g_Xl[i] = make_uint2((unsigned)l[0] | ((unsigned)l[1] << 16),
                                   (unsigned)l[2] | ((unsigned)l[3] << 16));
}

__global__ __launch_bounds__(256) void conv_w_kernel(
    const float* __restrict__ tw, const float* __restrict__ pw,
    const float* __restrict__ gw, const float* __restrict__ ww)
{
    const float* src; __nv_bfloat16* dh; __nv_bfloat16* dl;
    switch (blockIdx.y) {
        case 0: src = tw; dh = g_Twh; dl = g_Twl; break;
        case 1: src = pw; dh = g_Pwh; dl = g_Pwl; break;
        case 2: src = gw; dh = g_Gwh; dl = g_Gwl; break;
        default: src = ww; dh = g_Wwh; dl = g_Wwl; break;
    }
    size_t i = ((size_t)blockIdx.x * 256 + threadIdx.x) * 4;
    float4 v = *(const float4*)&src[i];
    unsigned short h[4], l[4];
    bfsplit(v.x, h[0], l[0]); bfsplit(v.y, h[1], l[1]);
    bfsplit(v.z, h[2], l[2]); bfsplit(v.w, h[3], l[3]);
    *(uint2*)&dh[i] = make_uint2((unsigned)h[0] | ((unsigned)h[1] << 16),
                                 (unsigned)h[2] | ((unsigned)h[3] << 16));
    *(uint2*)&dl[i] = make_uint2((unsigned)l[0] | ((unsigned)l[1] << 16),
                                 (unsigned)l[2] | ((unsigned)l[3] << 16));
}

// ---------------------------------------------------------------------------
// HMMA projections. grid (32,8,3), 256 threads.
// ---------------------------------------------------------------------------
#define PS_XH(s) ((s) * 65536u)
#define PS_XL(s) ((s) * 65536u + 16384u)
#define PS_WH(s) ((s) * 65536u + 32768u)
#define PS_WL(s) ((s) * 65536u + 49152u)
#define SMEM_PROJ 131072u

__global__ __launch_bounds__(256, 1) void proj_mma_kernel(
    const float* __restrict__ tb, const float* __restrict__ pb,
    const float* __restrict__ gb)
{
    extern __shared__ __align__(256) char sm[];
    const uint32_t su = s2u(sm);

    const int t = threadIdx.x;
    const int w = t >> 5;
    const int lane = t & 31;
    const int sub = lane >> 3;
    const int rowInM = lane & 7;
    const int b = blockIdx.y;
    const int which = blockIdx.z;
    const int n0 = blockIdx.x * 128;

    const __nv_bfloat16 *wh, *wl; const float* bias;
    if (which == 0)      { wh = g_Twh; wl = g_Twl; bias = tb; }
    else if (which == 1) { wh = g_Pwh; wl = g_Pwl; bias = pb; }
    else                 { wh = g_Gwh; wl = g_Gwl; bias = gb; }
    const __nv_bfloat16* xh = g_Xh + (size_t)b * CIN * NTOK;
    const __nv_bfloat16* xl = g_Xl + (size_t)b * CIN * NTOK;

    auto load_stage = [&](int c0, int s) {
        for (int i = t; i < 1024; i += 256) {
            int r = i >> 4, ch = i & 15;
            uint32_t off = swz(r, ch);
            size_t g = (size_t)(c0 + r) * NTOK + n0 + ch * 8;
            cp16(su + PS_XH(s) + off, xh + g);
            cp16(su + PS_XL(s) + off, xl + g);
        }
        for (int i = t; i < 1024; i += 256) {
            int r = i >> 3, ch = i & 7;
            uint32_t off = swzB(r, ch);
            size_t g = (size_t)r * CIN + c0 + ch * 8;
            cp16(su + PS_WH(s) + off, wh + g);
            cp16(su + PS_WL(s) + off, wl + g);
        }
    };

    float d[16][4];
    #pragma unroll
    for (int i = 0; i < 16; i++)
        #pragma unroll
        for (int j = 0; j < 4; j++) d[i][j] = 0.f;

    load_stage(0, 0);
    cp_commit();

    for (int ck = 0; ck < 4; ck++) {
        if (ck < 3) { load_stage((ck + 1) * 64, (ck + 1) & 1); cp_commit(); cp_wait1(); }
        else cp_wait0();
        __syncthreads();
        const int s = ck & 1;
        #pragma unroll
        for (int kc = 0; kc < 4; kc++) {
            uint32_t ah[4], al[4];
            {
                int row = kc * 16 + rowInM + ((sub >> 1) << 3);
                int c16 = w * 2 + (sub & 1);
                ldsm4t(ah, su + PS_XH(s) + swz(row, c16));
                ldsm4t(al, su + PS_XL(s) + swz(row, c16));
            }
            #pragma unroll
            for (int nbp = 0; nbp < 8; nbp++) {
                uint32_t bh[4], bl[4];
                int row = nbp * 16 + rowInM + ((sub >> 1) << 3);
                int c16 = kc * 2 + (sub & 1);
                ldsm4(bh, su + PS_WH(s) + swzB(row, c16));
                ldsm4(bl, su + PS_WL(s) + swzB(row, c16));
                mma_bf(d[nbp * 2],     ah, bh[0], bh[1]);
                mma_bf(d[nbp * 2],     ah, bl[0], bl[1]);
                mma_bf(d[nbp * 2],     al, bh[0], bh[1]);
                mma_bf(d[nbp * 2 + 1], ah, bh[2], bh[3]);
                mma_bf(d[nbp * 2 + 1], ah, bl[2], bl[3]);
                mma_bf(d[nbp * 2 + 1], al, bh[2], bh[3]);
            }
        }
        __syncthreads();
    }

    const int g = lane >> 2, tq = lane & 3;
    const size_t nlo = (size_t)(n0 + w * 16 + g);
    const size_t nhi = nlo + 8;
    if (which < 2) {
        __nv_bfloat16* oh = (which == 0 ? g_Qh : g_Kh) + (size_t)b * NTOK * CD;
        __nv_bfloat16* ol = (which == 0 ? g_Ql : g_Kl) + (size_t)b * NTOK * CD;
        #pragma unroll
        for (int nb = 0; nb < 16; nb++) {
            int k0 = nb * 8 + tq * 2;
            float2 bb = *(const float2*)&bias[k0];
            uint32_t h, l;
            split2(d[nb][0] + bb.x, d[nb][1] + bb.y, h, l);
            *(uint32_t*)&oh[nlo * CD + k0] = h;
            *(uint32_t*)&ol[nlo * CD + k0] = l;
            split2(d[nb][2] + bb.x, d[nb][3] + bb.y, h, l);
            *(uint32_t*)&oh[nhi * CD + k0] = h;
            *(uint32_t*)&ol[nhi * CD + k0] = l;
        }
    } else {
        __half* oh = g_Vh + (size_t)b * NTOK * CD;
        #pragma unroll
        for (int nb = 0; nb < 16; nb++) {
            int k0 = nb * 8 + tq * 2;
            float2 bb = *(const float2*)&bias[k0];
            *(uint32_t*)&oh[nlo * CD + k0] = pack_h2(d[nb][0] + bb.x, d[nb][1] + bb.y);
            *(uint32_t*)&oh[nhi * CD + k0] = pack_h2(d[nb][2] + bb.x, d[nb][3] + bb.y);
        }
    }
}

// ---------------------------------------------------------------------------
// HMMA flash attention. BQ=64, BK=64. grid (64, 8), 128 threads, 2 CTAs/SM.
// Q fragments live in registers; Q staging borrows the K smem buffers.
// smem: KH 2x16K @0, KL 2x16K @32K, VH 2x16K @64K  = 96 KB.
// ---------------------------------------------------------------------------
#define S_KH 0u
#define S_KL 32768u
#define S_VH 65536u
#define S_STG 16384u
#define SMEM_FLASH 98304u

__global__ __launch_bounds__(128, 2) void flash_mma_kernel()
{
    extern __shared__ __align__(256) char sm[];
    const uint32_t su = s2u(sm);

    const int t = threadIdx.x;
    const int w = t >> 5;
    const int lane = t & 31;
    const int sub = lane >> 3;
    const int rowInM = lane & 7;
    const int b = blockIdx.y;
    const int q0 = blockIdx.x * 64;

    const __nv_bfloat16* Qhg = g_Qh + ((size_t)b * NTOK + q0) * CD;
    const __nv_bfloat16* Qlg = g_Ql + ((size_t)b * NTOK + q0) * CD;
    const __nv_bfloat16* Khg = g_Kh + (size_t)b * NTOK * CD;
    const __nv_bfloat16* Klg = g_Kl + (size_t)b * NTOK * CD;
    const __half* Vhg = g_Vh + (size_t)b * NTOK * CD;

    // ---- stage Q through the K buffers, pull fragments to registers ----
    for (int i = t; i < 1024; i += 128) {
        int r = i >> 4, c = i & 15;
        uint32_t off = swz(r, c);
        cp16(su + S_KH + off,         Qhg + (size_t)r * CD + c * 8);
        cp16(su + S_KH + S_STG + off, Qlg + (size_t)r * CD + c * 8);
    }
    cp_commit(); cp_wait0();
    __syncthreads();

    uint32_t qh[8][4], ql[8][4];
    #pragma unroll
    for (int kc = 0; kc < 8; kc++) {
        int row = w * 16 + rowInM + ((sub & 1) << 3);
        int c16 = kc * 2 + (sub >> 1);
        ldsm4(qh[kc], su + S_KH + swz(row, c16));
        ldsm4(ql[kc], su + S_KH + S_STG + swz(row, c16));
    }
    __syncthreads();

    // ---- prefetch kt=0 ----
    for (int i = t; i < 1024; i += 128) {
        int r = i >> 4, c = i & 15;
        uint32_t off = swz(r, c);
        size_t g = (size_t)r * CD + c * 8;
        cp16(su + S_KH + off, Khg + g);
        cp16(su + S_KL + off, Klg + g);
        cp16(su + S_VH + off, Vhg + g);
    }
    cp_commit();

    float o[16][4];
    #pragma unroll
    for (int f = 0; f < 16; f++)
        #pragma unroll
        for (int j = 0; j < 4; j++) o[f][j] = 0.f;
    float m0 = -1e30f, m1 = -1e30f, l0 = 0.f, l1 = 0.f;

    for (int kt = 0; kt < NKT; kt++) {
        const uint32_t st = (kt & 1) * S_STG;
        if (kt + 1 < NKT) {
            const uint32_t st2 = ((kt + 1) & 1) * S_STG;
            const size_t gofs = (size_t)(kt + 1) * 64 * CD;
            for (int i = t; i < 1024; i += 128) {
                int r = i >> 4, c = i & 15;
                uint32_t off = swz(r, c) + st2;
                size_t g = gofs + (size_t)r * CD + c * 8;
                cp16(su + S_KH + off, Khg + g);
                cp16(su + S_KL + off, Klg + g);
                cp16(su + S_VH + off, Vhg + g);
            }
            cp_commit();
            cp_wait1();
        } else {
            cp_wait0();
        }
        __syncthreads();

        // ---------- S = Q K^T (bf16, 3 products; Q from registers) ----------
        float s[8][4];
        #pragma unroll
        for (int f = 0; f < 8; f++)
            #pragma unroll
            for (int j = 0; j < 4; j++) s[f][j] = 0.f;

        #pragma unroll
        for (int kc = 0; kc < 8; kc++) {
            #pragma unroll
            for (int nb = 0; nb < 4; nb++) {
                uint32_t kh4[4], kl4[4];
                int row = nb * 16 + rowInM + ((sub >> 1) << 3);
                int c16 = kc * 2 + (sub & 1);
                ldsm4(kh4, su + S_KH + st + swz(row, c16));
                ldsm4(kl4, su + S_KL + st + swz(row, c16));
                mma_bf(s[nb * 2],     qh[kc], kh4[0], kh4[1]);
                mma_bf(s[nb * 2 + 1], qh[kc], kh4[2], kh4[3]);
                mma_bf(s[nb * 2],     qh[kc], kl4[0], kl4[1]);
                mma_bf(s[nb * 2 + 1], qh[kc], kl4[2], kl4[3]);
                mma_bf(s[nb * 2],     ql[kc], kh4[0], kh4[1]);
                mma_bf(s[nb * 2 + 1], ql[kc], kh4[2], kh4[3]);
            }
        }

        // ---------- online softmax (rescale skipped when max stable) ----------
        float mx0 = -1e30f, mx1 = -1e30f;
        #pragma unroll
        for (int f = 0; f < 8; f++) {
            mx0 = fmaxf(mx0, fmaxf(s[f][0], s[f][1]));
            mx1 = fmaxf(mx1, fmaxf(s[f][2], s[f][3]));
        }
        mx0 = fmaxf(mx0, __shfl_xor_sync(0xffffffffu, mx0, 1));
        mx0 = fmaxf(mx0, __shfl_xor_sync(0xffffffffu, mx0, 2));
        mx1 = fmaxf(mx1, __shfl_xor_sync(0xffffffffu, mx1, 1));
        mx1 = fmaxf(mx1, __shfl_xor_sync(0xffffffffu, mx1, 2));

        uint32_t upd = __ballot_sync(0xffffffffu, (mx0 > m0) || (mx1 > m1));
        if (upd) {
            float mn0 = fmaxf(m0, mx0), mn1 = fmaxf(m1, mx1);
            float c0f = fexp(m0 - mn0), c1f = fexp(m1 - mn1);
            m0 = mn0; m1 = mn1;
            l0 *= c0f; l1 *= c1f;
            #pragma unroll
            for (int f = 0; f < 16; f++) {
                o[f][0] *= c0f; o[f][1] *= c0f;
                o[f][2] *= c1f; o[f][3] *= c1f;
            }
        }

        uint32_t ph0[8], ph1[8];
        float ps0 = 0.f, ps1 = 0.f;
        #pragma unroll
        for (int f = 0; f < 8; f++) {
            float p00 = fexp(s[f][0] - m0);
            float p01 = fexp(s[f][1] - m0);
            float p10 = fexp(s[f][2] - m1);
            float p11 = fexp(s[f][3] - m1);
            ps0 += p00 + p01;
            ps1 += p10 + p11;
            ph0[f] = pack_h2(p00, p01);
            ph1[f] = pack_h2(p10, p11);
        }
        ps0 += __shfl_xor_sync(0xffffffffu, ps0, 1);
        ps0 += __shfl_xor_sync(0xffffffffu, ps0, 2);
        ps1 += __shfl_xor_sync(0xffffffffu, ps1, 1);
        ps1 += __shfl_xor_sync(0xffffffffu, ps1, 2);
        l0 += ps0;
        l1 += ps1;

        // ---------- O += P V (fp16, single product) ----------
        #pragma unroll
        for (int kc = 0; kc < 4; kc++) {
            uint32_t a[4] = {ph0[kc * 2], ph1[kc * 2], ph0[kc * 2 + 1], ph1[kc * 2 + 1]};
            int row = kc * 16 + rowInM + ((sub & 1) << 3);
            #pragma unroll
            for (int vb = 0; vb < 8; vb++) {
                int c16 = vb * 2 + (sub >> 1);
                uint32_t vh4[4];
                ldsm4t(vh4, su + S_VH + st + swz(row, c16));
                mma_hf(o[vb * 2],     a, vh4[0], vh4[1]);
                mma_hf(o[vb * 2 + 1], a, vh4[2], vh4[3]);
            }
        }
        __syncthreads();
    }

    // ---------- normalize + store Y (bf16 hi/lo) ----------
    const float i0 = 1.f / l0, i1 = 1.f / l1;
    const int g = lane >> 2, tq = lane & 3;
    const size_t r0 = (size_t)b * NTOK + q0 + w * 16 + g;
    const size_t r1 = r0 + 8;
    #pragma unroll
    for (int f = 0; f < 16; f++) {
        int col = f * 8 + tq * 2;
        uint32_t h, l;
        split2(o[f][0] * i0, o[f][1] * i0, h, l);
        *(uint32_t*)&g_Yh[r0 * CD + col] = h;
        *(uint32_t*)&g_Yl[r0 * CD + col] = l;
        split2(o[f][2] * i1, o[f][3] * i1, h, l);
        *(uint32_t*)&g_Yh[r1 * CD + col] = h;
        *(uint32_t*)&g_Yl[r1 * CD + col] = l;
    }
}

// ---------------------------------------------------------------------------
// HMMA output conv. grid (32 n, 2 c, 8 b), 256 threads.
// ---------------------------------------------------------------------------
#define OS_WH 0u
#define OS_WL 32768u
#define OS_YH 65536u
#define OS_YL 98304u
#define SMEM_OUT 131072u

__global__ __launch_bounds__(256, 1) void out_mma_kernel(
    const float* __restrict__ wb, float* __restrict__ out)
{
    extern __shared__ __align__(256) char sm[];
    const uint32_t su = s2u(sm);

    const int t = threadIdx.x;
    const int w = t >> 5;
    const int lane = t & 31;
    const int sub = lane >> 3;
    const int rowInM = lane & 7;
    const int b = blockIdx.z;
    const int c0t = blockIdx.y * 128;
    const int n0 = blockIdx.x * 128;

    for (int i = t; i < 2048; i += 256) {
        int r = i >> 4, ch = i & 15;
        uint32_t off = swz(r, ch);
        size_t gw = (size_t)(c0t + r) * CD + ch * 8;
        size_t gy = ((size_t)b * NTOK + n0 + r) * CD + ch * 8;
        cp16(su + OS_WH + off, g_Wwh + gw);
        cp16(su + OS_WL + off, g_Wwl + gw);
        cp16(su + OS_YH + off, g_Yh + gy);
        cp16(su + OS_YL + off, g_Yl + gy);
    }
    cp_commit();
    cp_wait0();
    __syncthreads();

    float d[16][4];
    #pragma unroll
    for (int i = 0; i < 16; i++)
        #pragma unroll
        for (int j = 0; j < 4; j++) d[i][j] = 0.f;

    #pragma unroll
    for (int kc = 0; kc < 8; kc++) {
        uint32_t ah[4], al[4];
        {
            int row = w * 16 + rowInM + ((sub & 1) << 3);
            int c16 = kc * 2 + (sub >> 1);
            ldsm4(ah, su + OS_WH + swz(row, c16));
            ldsm4(al, su + OS_WL + swz(row, c16));
        }
        #pragma unroll
        for (int nbp = 0; nbp < 8; nbp++) {
            uint32_t yh[4], yl[4];
            int row = nbp * 16 + rowInM + ((sub >> 1) << 3);
            int c16 = kc * 2 + (sub & 1);
            ldsm4(yh, su + OS_YH + swz(row, c16));
            ldsm4(yl, su + OS_YL + swz(row, c16));
            mma_bf(d[nbp * 2],     ah, yh[0], yh[1]);
            mma_bf(d[nbp * 2],     ah, yl[0], yl[1]);
            mma_bf(d[nbp * 2],     al, yh[0], yh[1]);
            mma_bf(d[nbp * 2 + 1], ah, yh[2], yh[3]);
            mma_bf(d[nbp * 2 + 1], ah, yl[2], yl[3]);
            mma_bf(d[nbp * 2 + 1], al, yh[2], yh[3]);
        }
    }

    const int g = lane >> 2, tq = lane & 3;
    const int clo = c0t + w * 16 + g;
    const int chi = clo + 8;
    const float wb0 = wb[clo], wb1 = wb[chi];
    float* ob = out + (size_t)b * CIN * NTOK;
    #pragma unroll
    for (int nb = 0; nb < 16; nb++) {
        int n = n0 + nb * 8 + tq * 2;
        *(float2*)&ob[(size_t)clo * NTOK + n] = make_float2(d[nb][0] + wb0, d[nb][1] + wb0);
        *(float2*)&ob[(size_t)chi * NTOK + n] = make_float2(d[nb][2] + wb1, d[nb][3] + wb1);
    }
}

// ---------------------------------------------------------------------------
extern "C" void kernel_launch(void* const* d_in, const int* in_sizes, int n_in,
                              void* d_out, int out_size)
{
    const float* x  = (const float*)d_in[0];
    const float* tw = (const float*)d_in[1];
    const float* tb = (const float*)d_in[2];
    const float* pw = (const float*)d_in[3];
    const float* pb = (const float*)d_in[4];
    const float* gw = (const float*)d_in[5];
    const float* gb = (const float*)d_in[6];
    const float* ww = (const float*)d_in[7];
    const float* wb = (const float*)d_in[8];
    float* out = (float*)d_out;
    (void)in_sizes; (void)n_in; (void)out_size;

    conv_x_kernel<<<(BATCH * CIN * NTOK) / 1024, 256>>>(x);
    conv_w_kernel<<<dim3((CD * CIN) / 1024, 4), 256>>>(tw, pw, gw, ww);

    cudaFuncSetAttribute(proj_mma_kernel,
                         cudaFuncAttributeMaxDynamicSharedMemorySize, SMEM_PROJ);
    proj_mma_kernel<<<dim3(NTOK / 128, BATCH, 3), 256, SMEM_PROJ>>>(tb, pb, gb);

    cudaFuncSetAttribute(flash_mma_kernel,
                         cudaFuncAttributeMaxDynamicSharedMemorySize, SMEM_FLASH);
    flash_mma_kernel<<<dim3(NTOK / 64, BATCH), 128, SMEM_FLASH>>>();

    cudaFuncSetAttribute(out_mma_kernel,
                         cudaFuncAttributeMaxDynamicSharedMemorySize, SMEM_OUT);
    out_mma_kernel<<<dim3(NTOK / 128, CIN / 128, BATCH), 256, SMEM_OUT>>>(wb, out);
}

// round 10
// speedup vs baseline: 5.4373x; 1.1206x over previous
#include <cuda_runtime.h>
#include <cuda_bf16.h>
#include <cuda_fp16.h>
#include <cstdint>
#include <math.h>

#define BATCH 8
#define CIN   256
#define NTOK  4096
#define CD    128
#define NKT   64
#define LOG2E 1.4426950408889634f

// ---------------- device scratch ----------------
__device__ __nv_bfloat16 g_Xh[BATCH * CIN * NTOK];
__device__ __nv_bfloat16 g_Xl[BATCH * CIN * NTOK];
__device__ __nv_bfloat16 g_Twh[CD * CIN], g_Twl[CD * CIN];
__device__ __nv_bfloat16 g_Pwh[CD * CIN], g_Pwl[CD * CIN];
__device__ __nv_bfloat16 g_Gwh[CD * CIN], g_Gwl[CD * CIN];
__device__ __nv_bfloat16 g_Wwh[CIN * CD], g_Wwl[CIN * CD];
__device__ __nv_bfloat16 g_Qh[BATCH * NTOK * CD], g_Ql[BATCH * NTOK * CD];
__device__ __nv_bfloat16 g_Kh[BATCH * NTOK * CD], g_Kl[BATCH * NTOK * CD];
__device__ __half        g_Vh[BATCH * NTOK * CD];
__device__ __nv_bfloat16 g_Yh[BATCH * NTOK * CD], g_Yl[BATCH * NTOK * CD];

// ---------------- helpers ----------------
__device__ __forceinline__ uint32_t s2u(const void* p) {
    uint32_t a;
    asm("{ .reg .u64 t; cvta.to.shared.u64 t, %1; cvt.u32.u64 %0, t; }"
        : "=r"(a) : "l"(p));
    return a;
}
__device__ __forceinline__ void ldsm4(uint32_t* r, uint32_t a) {
    asm volatile("ldmatrix.sync.aligned.m8n8.x4.shared.b16 {%0,%1,%2,%3}, [%4];"
        : "=r"(r[0]), "=r"(r[1]), "=r"(r[2]), "=r"(r[3]) : "r"(a));
}
__device__ __forceinline__ void ldsm4t(uint32_t* r, uint32_t a) {
    asm volatile("ldmatrix.sync.aligned.m8n8.x4.trans.shared.b16 {%0,%1,%2,%3}, [%4];"
        : "=r"(r[0]), "=r"(r[1]), "=r"(r[2]), "=r"(r[3]) : "r"(a));
}
__device__ __forceinline__ void mma_bf(float* d, const uint32_t* a, uint32_t b0, uint32_t b1) {
    asm volatile(
        "mma.sync.aligned.m16n8k16.row.col.f32.bf16.bf16.f32 "
        "{%0,%1,%2,%3},{%4,%5,%6,%7},{%8,%9},{%0,%1,%2,%3};"
        : "+f"(d[0]), "+f"(d[1]), "+f"(d[2]), "+f"(d[3])
        : "r"(a[0]), "r"(a[1]), "r"(a[2]), "r"(a[3]), "r"(b0), "r"(b1));
}
__device__ __forceinline__ void mma_hf(float* d, const uint32_t* a, uint32_t b0, uint32_t b1) {
    asm volatile(
        "mma.sync.aligned.m16n8k16.row.col.f32.f16.f16.f32 "
        "{%0,%1,%2,%3},{%4,%5,%6,%7},{%8,%9},{%0,%1,%2,%3};"
        : "+f"(d[0]), "+f"(d[1]), "+f"(d[2]), "+f"(d[3])
        : "r"(a[0]), "r"(a[1]), "r"(a[2]), "r"(a[3]), "r"(b0), "r"(b1));
}
__device__ __forceinline__ void cp16(uint32_t dst, const void* src) {
    asm volatile("cp.async.cg.shared.global [%0], [%1], 16;" :: "r"(dst), "l"(src));
}
__device__ __forceinline__ void cp_commit() { asm volatile("cp.async.commit_group;"); }
__device__ __forceinline__ void cp_wait1() { asm volatile("cp.async.wait_group 1;" ::: "memory"); }
__device__ __forceinline__ void cp_wait0() { asm volatile("cp.async.wait_group 0;" ::: "memory"); }

__device__ __forceinline__ uint32_t swz(int r, int c16) {
    return (uint32_t)(r * 256 + ((c16 ^ (r & 7)) << 4));
}
__device__ __forceinline__ uint32_t swzB(int r, int c16) {
    return (uint32_t)(r * 128 + ((c16 ^ (r & 7)) << 4));
}

// MUFU exp2 (inputs arrive pre-scaled by log2e via Q scaling)
__device__ __forceinline__ float ex2(float x) {
    float y;
    asm("ex2.approx.ftz.f32 %0, %1;" : "=f"(y) : "f"(x));
    return y;
}

__device__ __forceinline__ void bfsplit(float v, unsigned short& h, unsigned short& l) {
    __nv_bfloat16 bh = __float2bfloat16_rn(v);
    __nv_bfloat16 bl = __float2bfloat16_rn(v - __bfloat162float(bh));
    h = __bfloat16_as_ushort(bh);
    l = __bfloat16_as_ushort(bl);
}
__device__ __forceinline__ void split2(float x, float y, uint32_t& h, uint32_t& l) {
    unsigned short hx, lx, hy, ly;
    bfsplit(x, hx, lx);
    bfsplit(y, hy, ly);
    h = (uint32_t)hx | ((uint32_t)hy << 16);
    l = (uint32_t)lx | ((uint32_t)ly << 16);
}
// pack (lo_elem, hi_elem) -> f16x2
__device__ __forceinline__ uint32_t pack_h2(float lo, float hi) {
    uint32_t r;
    asm("cvt.rn.f16x2.f32 %0, %1, %2;" : "=r"(r) : "f"(hi), "f"(lo));
    return r;
}

// ---------------------------------------------------------------------------
// conversion passes
// ---------------------------------------------------------------------------
__global__ __launch_bounds__(256) void conv_x_kernel(const float* __restrict__ x)
{
    size_t i = ((size_t)blockIdx.x * 256 + threadIdx.x) * 4;
    float4 v = *(const float4*)&x[i];
    unsigned short h[4], l[4];
    bfsplit(v.x, h[0], l[0]); bfsplit(v.y, h[1], l[1]);
    bfsplit(v.z, h[2], l[2]); bfsplit(v.w, h[3], l[3]);
    *(uint2*)&g_Xh[i] = make_uint2((unsigned)h[0] | ((unsigned)h[1] << 16),
                                   (unsigned)h[2] | ((unsigned)h[3] << 16));
    *(uint2*)&g_Xl[i] = make_uint2((unsigned)l[0] | ((unsigned)l[1] << 16),
                                   (unsigned)l[2] | ((unsigned)l[3] << 16));
}

__global__ __launch_bounds__(256) void conv_w_kernel(
    const float* __restrict__ tw, const float* __restrict__ pw,
    const float* __restrict__ gw, const float* __restrict__ ww)
{
    const float* src; __nv_bfloat16* dh; __nv_bfloat16* dl;
    switch (blockIdx.y) {
        case 0: src = tw; dh = g_Twh; dl = g_Twl; break;
        case 1: src = pw; dh = g_Pwh; dl = g_Pwl; break;
        case 2: src = gw; dh = g_Gwh; dl = g_Gwl; break;
        default: src = ww; dh = g_Wwh; dl = g_Wwl; break;
    }
    size_t i = ((size_t)blockIdx.x * 256 + threadIdx.x) * 4;
    float4 v = *(const float4*)&src[i];
    unsigned short h[4], l[4];
    bfsplit(v.x, h[0], l[0]); bfsplit(v.y, h[1], l[1]);
    bfsplit(v.z, h[2], l[2]); bfsplit(v.w, h[3], l[3]);
    *(uint2*)&dh[i] = make_uint2((unsigned)h[0] | ((unsigned)h[1] << 16),
                                 (unsigned)h[2] | ((unsigned)h[3] << 16));
    *(uint2*)&dl[i] = make_uint2((unsigned)l[0] | ((unsigned)l[1] << 16),
                                 (unsigned)l[2] | ((unsigned)l[3] << 16));
}

// ---------------------------------------------------------------------------
// HMMA projections. grid (32,8,3), 256 threads.
// Q output (which==0) is pre-scaled by LOG2E so S arrives in log2 domain.
// ---------------------------------------------------------------------------
#define PS_XH(s) ((s) * 65536u)
#define PS_XL(s) ((s) * 65536u + 16384u)
#define PS_WH(s) ((s) * 65536u + 32768u)
#define PS_WL(s) ((s) * 65536u + 49152u)
#define SMEM_PROJ 131072u

__global__ __launch_bounds__(256, 1) void proj_mma_kernel(
    const float* __restrict__ tb, const float* __restrict__ pb,
    const float* __restrict__ gb)
{
    extern __shared__ __align__(256) char sm[];
    const uint32_t su = s2u(sm);

    const int t = threadIdx.x;
    const int w = t >> 5;
    const int lane = t & 31;
    const int sub = lane >> 3;
    const int rowInM = lane & 7;
    const int b = blockIdx.y;
    const int which = blockIdx.z;
    const int n0 = blockIdx.x * 128;

    const __nv_bfloat16 *wh, *wl; const float* bias;
    if (which == 0)      { wh = g_Twh; wl = g_Twl; bias = tb; }
    else if (which == 1) { wh = g_Pwh; wl = g_Pwl; bias = pb; }
    else                 { wh = g_Gwh; wl = g_Gwl; bias = gb; }
    const __nv_bfloat16* xh = g_Xh + (size_t)b * CIN * NTOK;
    const __nv_bfloat16* xl = g_Xl + (size_t)b * CIN * NTOK;

    auto load_stage = [&](int c0, int s) {
        for (int i = t; i < 1024; i += 256) {
            int r = i >> 4, ch = i & 15;
            uint32_t off = swz(r, ch);
            size_t g = (size_t)(c0 + r) * NTOK + n0 + ch * 8;
            cp16(su + PS_XH(s) + off, xh + g);
            cp16(su + PS_XL(s) + off, xl + g);
        }
        for (int i = t; i < 1024; i += 256) {
            int r = i >> 3, ch = i & 7;
            uint32_t off = swzB(r, ch);
            size_t g = (size_t)r * CIN + c0 + ch * 8;
            cp16(su + PS_WH(s) + off, wh + g);
            cp16(su + PS_WL(s) + off, wl + g);
        }
    };

    float d[16][4];
    #pragma unroll
    for (int i = 0; i < 16; i++)
        #pragma unroll
        for (int j = 0; j < 4; j++) d[i][j] = 0.f;

    load_stage(0, 0);
    cp_commit();

    for (int ck = 0; ck < 4; ck++) {
        if (ck < 3) { load_stage((ck + 1) * 64, (ck + 1) & 1); cp_commit(); cp_wait1(); }
        else cp_wait0();
        __syncthreads();
        const int s = ck & 1;
        #pragma unroll
        for (int kc = 0; kc < 4; kc++) {
            uint32_t ah[4], al[4];
            {
                int row = kc * 16 + rowInM + ((sub >> 1) << 3);
                int c16 = w * 2 + (sub & 1);
                ldsm4t(ah, su + PS_XH(s) + swz(row, c16));
                ldsm4t(al, su + PS_XL(s) + swz(row, c16));
            }
            #pragma unroll
            for (int nbp = 0; nbp < 8; nbp++) {
                uint32_t bh[4], bl[4];
                int row = nbp * 16 + rowInM + ((sub >> 1) << 3);
                int c16 = kc * 2 + (sub & 1);
                ldsm4(bh, su + PS_WH(s) + swzB(row, c16));
                ldsm4(bl, su + PS_WL(s) + swzB(row, c16));
                mma_bf(d[nbp * 2],     ah, bh[0], bh[1]);
                mma_bf(d[nbp * 2],     ah, bl[0], bl[1]);
                mma_bf(d[nbp * 2],     al, bh[0], bh[1]);
                mma_bf(d[nbp * 2 + 1], ah, bh[2], bh[3]);
                mma_bf(d[nbp * 2 + 1], ah, bl[2], bl[3]);
                mma_bf(d[nbp * 2 + 1], al, bh[2], bh[3]);
            }
        }
        __syncthreads();
    }

    const int g = lane >> 2, tq = lane & 3;
    const size_t nlo = (size_t)(n0 + w * 16 + g);
    const size_t nhi = nlo + 8;
    const float sc = (which == 0) ? LOG2E : 1.f;
    if (which < 2) {
        __nv_bfloat16* oh = (which == 0 ? g_Qh : g_Kh) + (size_t)b * NTOK * CD;
        __nv_bfloat16* ol = (which == 0 ? g_Ql : g_Kl) + (size_t)b * NTOK * CD;
        #pragma unroll
        for (int nb = 0; nb < 16; nb++) {
            int k0 = nb * 8 + tq * 2;
            float2 bb = *(const float2*)&bias[k0];
            uint32_t h, l;
            split2((d[nb][0] + bb.x) * sc, (d[nb][1] + bb.y) * sc, h, l);
            *(uint32_t*)&oh[nlo * CD + k0] = h;
            *(uint32_t*)&ol[nlo * CD + k0] = l;
            split2((d[nb][2] + bb.x) * sc, (d[nb][3] + bb.y) * sc, h, l);
            *(uint32_t*)&oh[nhi * CD + k0] = h;
            *(uint32_t*)&ol[nhi * CD + k0] = l;
        }
    } else {
        __half* oh = g_Vh + (size_t)b * NTOK * CD;
        #pragma unroll
        for (int nb = 0; nb < 16; nb++) {
            int k0 = nb * 8 + tq * 2;
            float2 bb = *(const float2*)&bias[k0];
            *(uint32_t*)&oh[nlo * CD + k0] = pack_h2(d[nb][0] + bb.x, d[nb][1] + bb.y);
            *(uint32_t*)&oh[nhi * CD + k0] = pack_h2(d[nb][2] + bb.x, d[nb][3] + bb.y);
        }
    }
}

// ---------------------------------------------------------------------------
// HMMA flash attention. BQ=64, BK=64. grid (64, 8), 128 threads, 2 CTAs/SM.
// S is in log2 domain (Q pre-scaled); softmax = FADD + MUFU.EX2.
// ---------------------------------------------------------------------------
#define S_KH 0u
#define S_KL 32768u
#define S_VH 65536u
#define S_STG 16384u
#define SMEM_FLASH 98304u

__global__ __launch_bounds__(128, 2) void flash_mma_kernel()
{
    extern __shared__ __align__(256) char sm[];
    const uint32_t su = s2u(sm);

    const int t = threadIdx.x;
    const int w = t >> 5;
    const int lane = t & 31;
    const int sub = lane >> 3;
    const int rowInM = lane & 7;
    const int b = blockIdx.y;
    const int q0 = blockIdx.x * 64;

    const __nv_bfloat16* Qhg = g_Qh + ((size_t)b * NTOK + q0) * CD;
    const __nv_bfloat16* Qlg = g_Ql + ((size_t)b * NTOK + q0) * CD;
    const __nv_bfloat16* Khg = g_Kh + (size_t)b * NTOK * CD;
    const __nv_bfloat16* Klg = g_Kl + (size_t)b * NTOK * CD;
    const __half* Vhg = g_Vh + (size_t)b * NTOK * CD;

    // ---- stage Q through the K buffers, pull fragments to registers ----
    for (int i = t; i < 1024; i += 128) {
        int r = i >> 4, c = i & 15;
        uint32_t off = swz(r, c);
        cp16(su + S_KH + off,         Qhg + (size_t)r * CD + c * 8);
        cp16(su + S_KH + S_STG + off, Qlg + (size_t)r * CD + c * 8);
    }
    cp_commit(); cp_wait0();
    __syncthreads();

    uint32_t qh[8][4], ql[8][4];
    #pragma unroll
    for (int kc = 0; kc < 8; kc++) {
        int row = w * 16 + rowInM + ((sub & 1) << 3);
        int c16 = kc * 2 + (sub >> 1);
        ldsm4(qh[kc], su + S_KH + swz(row, c16));
        ldsm4(ql[kc], su + S_KH + S_STG + swz(row, c16));
    }
    __syncthreads();

    // ---- prefetch kt=0 ----
    for (int i = t; i < 1024; i += 128) {
        int r = i >> 4, c = i & 15;
        uint32_t off = swz(r, c);
        size_t g = (size_t)r * CD + c * 8;
        cp16(su + S_KH + off, Khg + g);
        cp16(su + S_KL + off, Klg + g);
        cp16(su + S_VH + off, Vhg + g);
    }
    cp_commit();

    float o[16][4];
    #pragma unroll
    for (int f = 0; f < 16; f++)
        #pragma unroll
        for (int j = 0; j < 4; j++) o[f][j] = 0.f;
    float m0 = -1e30f, m1 = -1e30f, l0 = 0.f, l1 = 0.f;

    for (int kt = 0; kt < NKT; kt++) {
        const uint32_t st = (kt & 1) * S_STG;
        if (kt + 1 < NKT) {
            const uint32_t st2 = ((kt + 1) & 1) * S_STG;
            const size_t gofs = (size_t)(kt + 1) * 64 * CD;
            for (int i = t; i < 1024; i += 128) {
                int r = i >> 4, c = i & 15;
                uint32_t off = swz(r, c) + st2;
                size_t g = gofs + (size_t)r * CD + c * 8;
                cp16(su + S_KH + off, Khg + g);
                cp16(su + S_KL + off, Klg + g);
                cp16(su + S_VH + off, Vhg + g);
            }
            cp_commit();
            cp_wait1();
        } else {
            cp_wait0();
        }
        __syncthreads();

        // ---------- S = Q K^T (bf16, 3 products; Q from registers) ----------
        float s[8][4];
        #pragma unroll
        for (int f = 0; f < 8; f++)
            #pragma unroll
            for (int j = 0; j < 4; j++) s[f][j] = 0.f;

        #pragma unroll
        for (int kc = 0; kc < 8; kc++) {
            #pragma unroll
            for (int nb = 0; nb < 4; nb++) {
                uint32_t kh4[4], kl4[4];
                int row = nb * 16 + rowInM + ((sub >> 1) << 3);
                int c16 = kc * 2 + (sub & 1);
                ldsm4(kh4, su + S_KH + st + swz(row, c16));
                ldsm4(kl4, su + S_KL + st + swz(row, c16));
                mma_bf(s[nb * 2],     qh[kc], kh4[0], kh4[1]);
                mma_bf(s[nb * 2 + 1], qh[kc], kh4[2], kh4[3]);
                mma_bf(s[nb * 2],     qh[kc], kl4[0], kl4[1]);
                mma_bf(s[nb * 2 + 1], qh[kc], kl4[2], kl4[3]);
                mma_bf(s[nb * 2],     ql[kc], kh4[0], kh4[1]);
                mma_bf(s[nb * 2 + 1], ql[kc], kh4[2], kh4[3]);
            }
        }

        // ---------- online softmax in log2 domain ----------
        float mx0 = -1e30f, mx1 = -1e30f;
        #pragma unroll
        for (int f = 0; f < 8; f++) {
            mx0 = fmaxf(mx0, fmaxf(s[f][0], s[f][1]));
            mx1 = fmaxf(mx1, fmaxf(s[f][2], s[f][3]));
        }
        mx0 = fmaxf(mx0, __shfl_xor_sync(0xffffffffu, mx0, 1));
        mx0 = fmaxf(mx0, __shfl_xor_sync(0xffffffffu, mx0, 2));
        mx1 = fmaxf(mx1, __shfl_xor_sync(0xffffffffu, mx1, 1));
        mx1 = fmaxf(mx1, __shfl_xor_sync(0xffffffffu, mx1, 2));

        uint32_t upd = __ballot_sync(0xffffffffu, (mx0 > m0) || (mx1 > m1));
        if (upd) {
            float mn0 = fmaxf(m0, mx0), mn1 = fmaxf(m1, mx1);
            float c0f = ex2(m0 - mn0), c1f = ex2(m1 - mn1);
            m0 = mn0; m1 = mn1;
            l0 *= c0f; l1 *= c1f;
            #pragma unroll
            for (int f = 0; f < 16; f++) {
                o[f][0] *= c0f; o[f][1] *= c0f;
                o[f][2] *= c1f; o[f][3] *= c1f;
            }
        }

        uint32_t ph0[8], ph1[8];
        float ps0 = 0.f, ps1 = 0.f;
        #pragma unroll
        for (int f = 0; f < 8; f++) {
            float p00 = ex2(s[f][0] - m0);
            float p01 = ex2(s[f][1] - m0);
            float p10 = ex2(s[f][2] - m1);
            float p11 = ex2(s[f][3] - m1);
            ps0 += p00 + p01;
            ps1 += p10 + p11;
            ph0[f] = pack_h2(p00, p01);
            ph1[f] = pack_h2(p10, p11);
        }
        ps0 += __shfl_xor_sync(0xffffffffu, ps0, 1);
        ps0 += __shfl_xor_sync(0xffffffffu, ps0, 2);
        ps1 += __shfl_xor_sync(0xffffffffu, ps1, 1);
        ps1 += __shfl_xor_sync(0xffffffffu, ps1, 2);
        l0 += ps0;
        l1 += ps1;

        // ---------- O += P V (fp16, single product) ----------
        #pragma unroll
        for (int kc = 0; kc < 4; kc++) {
            uint32_t a[4] = {ph0[kc * 2], ph1[kc * 2], ph0[kc * 2 + 1], ph1[kc * 2 + 1]};
            int row = kc * 16 + rowInM + ((sub & 1) << 3);
            #pragma unroll
            for (int vb = 0; vb < 8; vb++) {
                int c16 = vb * 2 + (sub >> 1);
                uint32_t vh4[4];
                ldsm4t(vh4, su + S_VH + st + swz(row, c16));
                mma_hf(o[vb * 2],     a, vh4[0], vh4[1]);
                mma_hf(o[vb * 2 + 1], a, vh4[2], vh4[3]);
            }
        }
        __syncthreads();
    }

    // ---------- normalize + store Y (bf16 hi/lo) ----------
    const float i0 = 1.f / l0, i1 = 1.f / l1;
    const int g = lane >> 2, tq = lane & 3;
    const size_t r0 = (size_t)b * NTOK + q0 + w * 16 + g;
    const size_t r1 = r0 + 8;
    #pragma unroll
    for (int f = 0; f < 16; f++) {
        int col = f * 8 + tq * 2;
        uint32_t h, l;
        split2(o[f][0] * i0, o[f][1] * i0, h, l);
        *(uint32_t*)&g_Yh[r0 * CD + col] = h;
        *(uint32_t*)&g_Yl[r0 * CD + col] = l;
        split2(o[f][2] * i1, o[f][3] * i1, h, l);
        *(uint32_t*)&g_Yh[r1 * CD + col] = h;
        *(uint32_t*)&g_Yl[r1 * CD + col] = l;
    }
}

// ---------------------------------------------------------------------------
// HMMA output conv. grid (32 n, 2 c, 8 b), 256 threads.
// ---------------------------------------------------------------------------
#define OS_WH 0u
#define OS_WL 32768u
#define OS_YH 65536u
#define OS_YL 98304u
#define SMEM_OUT 131072u

__global__ __launch_bounds__(256, 1) void out_mma_kernel(
    const float* __restrict__ wb, float* __restrict__ out)
{
    extern __shared__ __align__(256) char sm[];
    const uint32_t su = s2u(sm);

    const int t = threadIdx.x;
    const int w = t >> 5;
    const int lane = t & 31;
    const int sub = lane >> 3;
    const int rowInM = lane & 7;
    const int b = blockIdx.z;
    const int c0t = blockIdx.y * 128;
    const int n0 = blockIdx.x * 128;

    for (int i = t; i < 2048; i += 256) {
        int r = i >> 4, ch = i & 15;
        uint32_t off = swz(r, ch);
        size_t gw = (size_t)(c0t + r) * CD + ch * 8;
        size_t gy = ((size_t)b * NTOK + n0 + r) * CD + ch * 8;
        cp16(su + OS_WH + off, g_Wwh + gw);
        cp16(su + OS_WL + off, g_Wwl + gw);
        cp16(su + OS_YH + off, g_Yh + gy);
        cp16(su + OS_YL + off, g_Yl + gy);
    }
    cp_commit();
    cp_wait0();
    __syncthreads();

    float d[16][4];
    #pragma unroll
    for (int i = 0; i < 16; i++)
        #pragma unroll
        for (int j = 0; j < 4; j++) d[i][j] = 0.f;

    #pragma unroll
    for (int kc = 0; kc < 8; kc++) {
        uint32_t ah[4], al[4];
        {
            int row = w * 16 + rowInM + ((sub & 1) << 3);
            int c16 = kc * 2 + (sub >> 1);
            ldsm4(ah, su + OS_WH + swz(row, c16));
            ldsm4(al, su + OS_WL + swz(row, c16));
        }
        #pragma unroll
        for (int nbp = 0; nbp < 8; nbp++) {
            uint32_t yh[4], yl[4];
            int row = nbp * 16 + rowInM + ((sub >> 1) << 3);
            int c16 = kc * 2 + (sub & 1);
            ldsm4(yh, su + OS_YH + swz(row, c16));
            ldsm4(yl, su + OS_YL + swz(row, c16));
            mma_bf(d[nbp * 2],     ah, yh[0], yh[1]);
            mma_bf(d[nbp * 2],     ah, yl[0], yl[1]);
            mma_bf(d[nbp * 2],     al, yh[0], yh[1]);
            mma_bf(d[nbp * 2 + 1], ah, yh[2], yh[3]);
            mma_bf(d[nbp * 2 + 1], ah, yl[2], yl[3]);
            mma_bf(d[nbp * 2 + 1], al, yh[2], yh[3]);
        }
    }

    const int g = lane >> 2, tq = lane & 3;
    const int clo = c0t + w * 16 + g;
    const int chi = clo + 8;
    const float wb0 = wb[clo], wb1 = wb[chi];
    float* ob = out + (size_t)b * CIN * NTOK;
    #pragma unroll
    for (int nb = 0; nb < 16; nb++) {
        int n = n0 + nb * 8 + tq * 2;
        *(float2*)&ob[(size_t)clo * NTOK + n] = make_float2(d[nb][0] + wb0, d[nb][1] + wb0);
        *(float2*)&ob[(size_t)chi * NTOK + n] = make_float2(d[nb][2] + wb1, d[nb][3] + wb1);
    }
}

// ---------------------------------------------------------------------------
extern "C" void kernel_launch(void* const* d_in, const int* in_sizes, int n_in,
                              void* d_out, int out_size)
{
    const float* x  = (const float*)d_in[0];
    const float* tw = (const float*)d_in[1];
    const float* tb = (const float*)d_in[2];
    const float* pw = (const float*)d_in[3];
    const float* pb = (const float*)d_in[4];
    const float* gw = (const float*)d_in[5];
    const float* gb = (const float*)d_in[6];
    const float* ww = (const float*)d_in[7];
    const float* wb = (const float*)d_in[8];
    float* out = (float*)d_out;
    (void)in_sizes; (void)n_in; (void)out_size;

    conv_x_kernel<<<(BATCH * CIN * NTOK) / 1024, 256>>>(x);
    conv_w_kernel<<<dim3((CD * CIN) / 1024, 4), 256>>>(tw, pw, gw, ww);

    cudaFuncSetAttribute(proj_mma_kernel,
                         cudaFuncAttributeMaxDynamicSharedMemorySize, SMEM_PROJ);
    proj_mma_kernel<<<dim3(NTOK / 128, BATCH, 3), 256, SMEM_PROJ>>>(tb, pb, gb);

    cudaFuncSetAttribute(flash_mma_kernel,
                         cudaFuncAttributeMaxDynamicSharedMemorySize, SMEM_FLASH);
    flash_mma_kernel<<<dim3(NTOK / 64, BATCH), 128, SMEM_FLASH>>>();

    cudaFuncSetAttribute(out_mma_kernel,
                         cudaFuncAttributeMaxDynamicSharedMemorySize, SMEM_OUT);
    out_mma_kernel<<<dim3(NTOK / 128, CIN / 128, BATCH), 256, SMEM_OUT>>>(wb, out);
}